// round 1
// baseline (speedup 1.0000x reference)
#include <cuda_runtime.h>

#define E_       8
#define TOPK_    2
#define HID_     1024
#define FFN_     2048
#define M_TOK    2048
#define NSLOT    (M_TOK * TOPK_)      // 4096
#define OUT_MAIN (M_TOK * HID_)       // 2097152

#define BM 64
#define BN 64
#define BK 16
#define LDSW 68   // padded smem row stride (floats), keeps 16B alignment

// ---------------- device scratch (no allocations allowed) ----------------
__device__ int   g_cnt[E_];
__device__ int   g_off[E_ + 1];
__device__ int   g_cur[E_];
__device__ int   g_slot_e[NSLOT];
__device__ float g_slot_w[NSLOT];
__device__ int   g_tok[NSLOT];            // token index per grouped row
__device__ float g_w[NSLOT];              // combine weight per grouped row
__device__ float g_h[(size_t)NSLOT * FFN_];  // 32 MB intermediate h

// ---------------- init: zero counters + output region ----------------
__global__ void k_init(float* __restrict__ out) {
    int i = blockIdx.x * blockDim.x + threadIdx.x;
    if (i < E_) g_cnt[i] = 0;
    for (int j = i; j < OUT_MAIN; j += gridDim.x * blockDim.x) out[j] = 0.0f;
}

// ---------------- router: one warp per token ----------------
__global__ void k_router(const float* __restrict__ x,
                         const float* __restrict__ rw,
                         const float* __restrict__ rb,
                         float* __restrict__ out) {
    int warp = (blockIdx.x * blockDim.x + threadIdx.x) >> 5;
    int lane = threadIdx.x & 31;
    if (warp >= M_TOK) return;

    const float* xr = x + (size_t)warp * HID_;
    float xv[32];
#pragma unroll
    for (int i = 0; i < 32; i++) xv[i] = xr[lane + 32 * i];

    float logits[E_];
#pragma unroll
    for (int e = 0; e < E_; e++) {
        const float* w = rw + (size_t)e * HID_;
        float acc = 0.0f;
#pragma unroll
        for (int i = 0; i < 32; i++) acc += xv[i] * w[lane + 32 * i];
#pragma unroll
        for (int o = 16; o > 0; o >>= 1) acc += __shfl_xor_sync(0xffffffffu, acc, o);
        logits[e] = acc + rb[e];
    }

    if (lane == 0) {
        float mx = logits[0];
#pragma unroll
        for (int e = 1; e < E_; e++) mx = fmaxf(mx, logits[e]);
        float p[E_], s = 0.0f;
#pragma unroll
        for (int e = 0; e < E_; e++) { p[e] = expf(logits[e] - mx); s += p[e]; }
        float inv = 1.0f / s;
#pragma unroll
        for (int e = 0; e < E_; e++) p[e] *= inv;

        // top-2, descending, ties -> lower index (matches jax.lax.top_k)
        int i0 = 0;
#pragma unroll
        for (int e = 1; e < E_; e++) if (p[e] > p[i0]) i0 = e;
        int i1 = -1;
#pragma unroll
        for (int e = 0; e < E_; e++) {
            if (e == i0) continue;
            if (i1 < 0 || p[e] > p[i1]) i1 = e;
        }

        out[OUT_MAIN + warp * 2 + 0] = p[i0];
        out[OUT_MAIN + warp * 2 + 1] = p[i1];
        g_slot_e[warp * 2 + 0] = i0;  g_slot_w[warp * 2 + 0] = p[i0];
        g_slot_e[warp * 2 + 1] = i1;  g_slot_w[warp * 2 + 1] = p[i1];
        atomicAdd(&g_cnt[i0], 1);
        atomicAdd(&g_cnt[i1], 1);
    }
}

// ---------------- exclusive scan over 8 counts ----------------
__global__ void k_scan() {
    if (threadIdx.x == 0) {
        int s = 0;
        for (int e = 0; e < E_; e++) { g_off[e] = s; g_cur[e] = s; s += g_cnt[e]; }
        g_off[E_] = s;
    }
}

// ---------------- place slots into expert groups ----------------
__global__ void k_place() {
    int s = blockIdx.x * blockDim.x + threadIdx.x;
    if (s >= NSLOT) return;
    int e = g_slot_e[s];
    int p = atomicAdd(&g_cur[e], 1);
    g_tok[p] = s >> 1;
    g_w[p]   = g_slot_w[s];
}

// ---------------- GEMM1: h = silu(x@Wg^T + bg) * (x@Wu^T + bu) ----------------
// grid: (FFN/BN, M_TOK/BM, E), block 256
__global__ void k_gemm1(const float* __restrict__ x,
                        const float* __restrict__ w1,
                        const float* __restrict__ w1b) {
    int e = blockIdx.z;
    int rowEnd = g_off[e + 1];
    int row0 = g_off[e] + blockIdx.y * BM;
    if (row0 >= rowEnd) return;
    int nb = blockIdx.x * BN;

    __shared__ float As[BK][LDSW];
    __shared__ float Bg[BK][LDSW];
    __shared__ float Bu[BK][LDSW];

    int tid = threadIdx.x;
    int lr = tid >> 2;            // 0..63 row within tile
    int lk = (tid & 3) * 4;       // k offset 0,4,8,12

    int grow = row0 + lr;
    int crow = grow < rowEnd ? grow : (rowEnd - 1);     // clamp (masked later)
    const float* xrow = x + (size_t)g_tok[crow] * HID_;
    const float* wg = w1 + ((size_t)e * 2 * FFN_ + (nb + lr)) * HID_;
    const float* wu = wg + (size_t)FFN_ * HID_;

    float accg[4][4], accu[4][4];
#pragma unroll
    for (int i = 0; i < 4; i++)
#pragma unroll
        for (int j = 0; j < 4; j++) { accg[i][j] = 0.0f; accu[i][j] = 0.0f; }

    int tx = tid & 15;   // n-dir
    int ty = tid >> 4;   // m-dir

    for (int k0 = 0; k0 < HID_; k0 += BK) {
        float4 av = *(const float4*)(xrow + k0 + lk);
        float4 gv = *(const float4*)(wg + k0 + lk);
        float4 uv = *(const float4*)(wu + k0 + lk);
        __syncthreads();
        As[lk + 0][lr] = av.x; As[lk + 1][lr] = av.y; As[lk + 2][lr] = av.z; As[lk + 3][lr] = av.w;
        Bg[lk + 0][lr] = gv.x; Bg[lk + 1][lr] = gv.y; Bg[lk + 2][lr] = gv.z; Bg[lk + 3][lr] = gv.w;
        Bu[lk + 0][lr] = uv.x; Bu[lk + 1][lr] = uv.y; Bu[lk + 2][lr] = uv.z; Bu[lk + 3][lr] = uv.w;
        __syncthreads();
#pragma unroll
        for (int kk = 0; kk < BK; kk++) {
            float4 a  = *(const float4*)&As[kk][ty * 4];
            float4 bg = *(const float4*)&Bg[kk][tx * 4];
            float4 bu = *(const float4*)&Bu[kk][tx * 4];
            float am[4] = {a.x, a.y, a.z, a.w};
            float gm[4] = {bg.x, bg.y, bg.z, bg.w};
            float um[4] = {bu.x, bu.y, bu.z, bu.w};
#pragma unroll
            for (int i = 0; i < 4; i++)
#pragma unroll
                for (int j = 0; j < 4; j++) {
                    accg[i][j] += am[i] * gm[j];
                    accu[i][j] += am[i] * um[j];
                }
        }
    }

#pragma unroll
    for (int i = 0; i < 4; i++) {
        int r = row0 + ty * 4 + i;
        if (r >= rowEnd) continue;
#pragma unroll
        for (int j = 0; j < 4; j++) {
            int n = nb + tx * 4 + j;
            float g = accg[i][j] + w1b[(size_t)e * 2 * FFN_ + n];
            float u = accu[i][j] + w1b[(size_t)e * 2 * FFN_ + FFN_ + n];
            float hv = (g / (1.0f + expf(-g))) * u;
            g_h[(size_t)r * FFN_ + n] = hv;
        }
    }
}

// ---------------- GEMM2: out[tok] += w * (h@W2^T + b2) ----------------
// grid: (HID/BN, M_TOK/BM, E), block 256
__global__ void k_gemm2(const float* __restrict__ w2,
                        const float* __restrict__ w2b,
                        float* __restrict__ out) {
    int e = blockIdx.z;
    int rowEnd = g_off[e + 1];
    int row0 = g_off[e] + blockIdx.y * BM;
    if (row0 >= rowEnd) return;
    int nb = blockIdx.x * BN;

    __shared__ float As[BK][LDSW];
    __shared__ float Bs[BK][LDSW];

    int tid = threadIdx.x;
    int lr = tid >> 2;
    int lk = (tid & 3) * 4;

    int grow = row0 + lr;
    int crow = grow < rowEnd ? grow : (rowEnd - 1);
    const float* hrow = g_h + (size_t)crow * FFN_;
    const float* brow = w2 + ((size_t)e * HID_ + (nb + lr)) * FFN_;

    float acc[4][4];
#pragma unroll
    for (int i = 0; i < 4; i++)
#pragma unroll
        for (int j = 0; j < 4; j++) acc[i][j] = 0.0f;

    int tx = tid & 15;
    int ty = tid >> 4;

    for (int k0 = 0; k0 < FFN_; k0 += BK) {
        float4 av = *(const float4*)(hrow + k0 + lk);
        float4 bv = *(const float4*)(brow + k0 + lk);
        __syncthreads();
        As[lk + 0][lr] = av.x; As[lk + 1][lr] = av.y; As[lk + 2][lr] = av.z; As[lk + 3][lr] = av.w;
        Bs[lk + 0][lr] = bv.x; Bs[lk + 1][lr] = bv.y; Bs[lk + 2][lr] = bv.z; Bs[lk + 3][lr] = bv.w;
        __syncthreads();
#pragma unroll
        for (int kk = 0; kk < BK; kk++) {
            float4 a = *(const float4*)&As[kk][ty * 4];
            float4 b = *(const float4*)&Bs[kk][tx * 4];
            float am[4] = {a.x, a.y, a.z, a.w};
            float bm[4] = {b.x, b.y, b.z, b.w};
#pragma unroll
            for (int i = 0; i < 4; i++)
#pragma unroll
                for (int j = 0; j < 4; j++) acc[i][j] += am[i] * bm[j];
        }
    }

#pragma unroll
    for (int i = 0; i < 4; i++) {
        int r = row0 + ty * 4 + i;
        if (r >= rowEnd) continue;
        int tok = g_tok[r];
        float w = g_w[r];
#pragma unroll
        for (int j = 0; j < 4; j++) {
            int n = nb + tx * 4 + j;
            float val = (acc[i][j] + w2b[(size_t)e * HID_ + n]) * w;
            atomicAdd(&out[(size_t)tok * HID_ + n], val);
        }
    }
}

// ---------------- launch ----------------
extern "C" void kernel_launch(void* const* d_in, const int* in_sizes, int n_in,
                              void* d_out, int out_size) {
    (void)in_sizes; (void)n_in; (void)out_size;
    const float* x   = (const float*)d_in[0];
    const float* rw  = (const float*)d_in[1];
    const float* rb  = (const float*)d_in[2];
    const float* w1  = (const float*)d_in[3];
    const float* w1b = (const float*)d_in[4];
    const float* w2  = (const float*)d_in[5];
    const float* w2b = (const float*)d_in[6];
    float* out = (float*)d_out;

    k_init<<<1024, 256>>>(out);
    k_router<<<M_TOK / 8, 256>>>(x, rw, rb, out);
    k_scan<<<1, 32>>>();
    k_place<<<NSLOT / 256, 256>>>();

    dim3 g1(FFN_ / BN, M_TOK / BM, E_);
    k_gemm1<<<g1, 256>>>(x, w1, w1b);

    dim3 g2(HID_ / BN, M_TOK / BM, E_);
    k_gemm2<<<g2, 256>>>(w2, w2b, out);
}

// round 2
// speedup vs baseline: 2.8203x; 2.8203x over previous
#include <cuda_runtime.h>
#include <cstdint>

#define E_       8
#define TOPK_    2
#define HID_     1024
#define FFN_     2048
#define M_TOK    2048
#define NSLOT    (M_TOK * TOPK_)      // 4096
#define OUT_MAIN (M_TOK * HID_)       // 2097152

#define BM   128
#define BK   16
#define LDS_ 20     // padded smem row stride in floats (80B, 16B-aligned)

// ---------------- device scratch ----------------
__device__ int   g_cnt[E_];
__device__ int   g_off[E_ + 1];
__device__ int   g_cur[E_];
__device__ int   g_slot_e[NSLOT];
__device__ float g_slot_w[NSLOT];
__device__ int   g_tok[NSLOT];
__device__ float g_w[NSLOT];
__device__ float g_h[(size_t)NSLOT * FFN_];  // 32 MB intermediate

// ---------------- small helpers ----------------
__device__ __forceinline__ uint32_t f2tf(float f) {
    uint32_t r;
    asm("cvt.rna.tf32.f32 %0, %1;" : "=r"(r) : "f"(f));
    return r;
}

__device__ __forceinline__ void mma_tf32(float* d, const uint32_t* a,
                                         const uint32_t* b, const float* c) {
    asm volatile(
        "mma.sync.aligned.m16n8k8.row.col.f32.tf32.tf32.f32 "
        "{%0,%1,%2,%3}, {%4,%5,%6,%7}, {%8,%9}, {%10,%11,%12,%13};\n"
        : "=f"(d[0]), "=f"(d[1]), "=f"(d[2]), "=f"(d[3])
        : "r"(a[0]), "r"(a[1]), "r"(a[2]), "r"(a[3]),
          "r"(b[0]), "r"(b[1]),
          "f"(c[0]), "f"(c[1]), "f"(c[2]), "f"(c[3]));
}

__device__ __forceinline__ void cpa16(void* smem, const void* g) {
    uint32_t s = (uint32_t)__cvta_generic_to_shared(smem);
    asm volatile("cp.async.cg.shared.global [%0], [%1], 16;\n" :: "r"(s), "l"(g));
}
__device__ __forceinline__ void cpa_commit() {
    asm volatile("cp.async.commit_group;\n");
}
__device__ __forceinline__ void cpa_wait1() {
    asm volatile("cp.async.wait_group 1;\n");
}
__device__ __forceinline__ void cpa_wait0() {
    asm volatile("cp.async.wait_group 0;\n");
}

// ---------------- init: zero counters + output region ----------------
__global__ void k_init(float* __restrict__ out) {
    int i = blockIdx.x * blockDim.x + threadIdx.x;
    if (i < E_) g_cnt[i] = 0;
    for (int j = i; j < OUT_MAIN; j += gridDim.x * blockDim.x) out[j] = 0.0f;
}

// ---------------- router: one warp per token ----------------
__global__ void k_router(const float* __restrict__ x,
                         const float* __restrict__ rw,
                         const float* __restrict__ rb,
                         float* __restrict__ out) {
    int warp = (blockIdx.x * blockDim.x + threadIdx.x) >> 5;
    int lane = threadIdx.x & 31;
    if (warp >= M_TOK) return;

    const float* xr = x + (size_t)warp * HID_;
    float xv[32];
#pragma unroll
    for (int i = 0; i < 32; i++) xv[i] = xr[lane + 32 * i];

    float logits[E_];
#pragma unroll
    for (int e = 0; e < E_; e++) {
        const float* w = rw + (size_t)e * HID_;
        float acc = 0.0f;
#pragma unroll
        for (int i = 0; i < 32; i++) acc += xv[i] * w[lane + 32 * i];
#pragma unroll
        for (int o = 16; o > 0; o >>= 1) acc += __shfl_xor_sync(0xffffffffu, acc, o);
        logits[e] = acc + rb[e];
    }

    if (lane == 0) {
        float mx = logits[0];
#pragma unroll
        for (int e = 1; e < E_; e++) mx = fmaxf(mx, logits[e]);
        float p[E_], s = 0.0f;
#pragma unroll
        for (int e = 0; e < E_; e++) { p[e] = expf(logits[e] - mx); s += p[e]; }
        float inv = 1.0f / s;
#pragma unroll
        for (int e = 0; e < E_; e++) p[e] *= inv;

        int i0 = 0;
#pragma unroll
        for (int e = 1; e < E_; e++) if (p[e] > p[i0]) i0 = e;
        int i1 = -1;
#pragma unroll
        for (int e = 0; e < E_; e++) {
            if (e == i0) continue;
            if (i1 < 0 || p[e] > p[i1]) i1 = e;
        }

        out[OUT_MAIN + warp * 2 + 0] = p[i0];
        out[OUT_MAIN + warp * 2 + 1] = p[i1];
        g_slot_e[warp * 2 + 0] = i0;  g_slot_w[warp * 2 + 0] = p[i0];
        g_slot_e[warp * 2 + 1] = i1;  g_slot_w[warp * 2 + 1] = p[i1];
        atomicAdd(&g_cnt[i0], 1);
        atomicAdd(&g_cnt[i1], 1);
    }
}

__global__ void k_scan() {
    if (threadIdx.x == 0) {
        int s = 0;
        for (int e = 0; e < E_; e++) { g_off[e] = s; g_cur[e] = s; s += g_cnt[e]; }
        g_off[E_] = s;
    }
}

__global__ void k_place() {
    int s = blockIdx.x * blockDim.x + threadIdx.x;
    if (s >= NSLOT) return;
    int e = g_slot_e[s];
    int p = atomicAdd(&g_cur[e], 1);
    g_tok[p] = s >> 1;
    g_w[p]   = g_slot_w[s];
}

// ============================================================================
// GEMM1 (tf32 tensor cores): h = silu(x@Wg^T + bg) * (x@Wu^T + bu)
// Block tile: 128 rows x 64 h-columns (B tile = 128 interleaved gate/up rows).
// grid: (FFN/64, 16, E), block 256 (8 warps, 2x4; warp tile 64x32)
// ============================================================================
__global__ void __launch_bounds__(256)
k_gemm1(const float* __restrict__ x,
        const float* __restrict__ w1,
        const float* __restrict__ w1b) {
    int e = blockIdx.z;
    int rowEnd = g_off[e + 1];
    int row0 = g_off[e] + blockIdx.y * BM;
    if (row0 >= rowEnd) return;
    int nb = blockIdx.x * 64;   // h-column base (gate col base)

    __shared__ float As[2][BM][LDS_];
    __shared__ float Bs[2][BM][LDS_];

    int tid  = threadIdx.x;
    int lane = tid & 31;
    int wid  = tid >> 5;
    int wm   = wid >> 2;   // 0..1
    int wn   = wid & 3;    // 0..3

    // --- per-thread load descriptors (2 float4 per tile per array) ---
    // tile has 128 rows x 4 float4 (BK=16). idx = tid + 256*p -> row=idx/4, c4=idx%4
    const float* aptr[2];
    const float* bptr[2];
    int ac4[2];
#pragma unroll
    for (int p = 0; p < 2; p++) {
        int idx = tid + 256 * p;
        int r   = idx >> 2;
        ac4[p]  = (idx & 3) * 4;
        int gr  = row0 + r;
        if (gr >= rowEnd) gr = rowEnd - 1;
        aptr[p] = x + (size_t)g_tok[gr] * HID_;
        // B tile: even row -> gate(nb + r/2), odd row -> up(FFN + nb + r/2)
        int wrow = (size_t)e * 2 * FFN_ + ((r & 1) ? (FFN_ + nb + (r >> 1)) : (nb + (r >> 1)));
        bptr[p] = w1 + (size_t)wrow * HID_;
    }

    auto load_tile = [&](int buf, int k0) {
#pragma unroll
        for (int p = 0; p < 2; p++) {
            int idx = tid + 256 * p;
            int r   = idx >> 2;
            cpa16(&As[buf][r][ac4[p]], aptr[p] + k0 + ac4[p]);
            cpa16(&Bs[buf][r][ac4[p]], bptr[p] + k0 + ac4[p]);
        }
        cpa_commit();
    };

    float acc[4][4][4];
#pragma unroll
    for (int mi = 0; mi < 4; mi++)
#pragma unroll
        for (int ni = 0; ni < 4; ni++)
#pragma unroll
            for (int q = 0; q < 4; q++) acc[mi][ni][q] = 0.0f;

    const int NIT = HID_ / BK;   // 64
    load_tile(0, 0);

    int lr = lane >> 2;   // 0..7
    int lc = lane & 3;    // 0..3

    for (int it = 0; it < NIT; it++) {
        int buf = it & 1;
        if (it + 1 < NIT) { load_tile(buf ^ 1, (it + 1) * BK); cpa_wait1(); }
        else              { cpa_wait0(); }
        __syncthreads();

#pragma unroll
        for (int s = 0; s < 2; s++) {
            int k0 = s * 8;
            uint32_t a[4][4], b[4][2];
#pragma unroll
            for (int mi = 0; mi < 4; mi++) {
                int r = wm * 64 + mi * 16 + lr;
                a[mi][0] = f2tf(As[buf][r][k0 + lc]);
                a[mi][1] = f2tf(As[buf][r + 8][k0 + lc]);
                a[mi][2] = f2tf(As[buf][r][k0 + lc + 4]);
                a[mi][3] = f2tf(As[buf][r + 8][k0 + lc + 4]);
            }
#pragma unroll
            for (int ni = 0; ni < 4; ni++) {
                int n = wn * 32 + ni * 8 + lr;
                b[ni][0] = f2tf(Bs[buf][n][k0 + lc]);
                b[ni][1] = f2tf(Bs[buf][n][k0 + lc + 4]);
            }
#pragma unroll
            for (int mi = 0; mi < 4; mi++)
#pragma unroll
                for (int ni = 0; ni < 4; ni++)
                    mma_tf32(acc[mi][ni], a[mi], b[ni], acc[mi][ni]);
        }
        __syncthreads();
    }

    // --- epilogue: fuse bias + silu*up, write h ---
    const float* bg_base = w1b + (size_t)e * 2 * FFN_;
    const float* bu_base = bg_base + FFN_;
#pragma unroll
    for (int mi = 0; mi < 4; mi++) {
        int r = row0 + wm * 64 + mi * 16 + lr;
#pragma unroll
        for (int ni = 0; ni < 4; ni++) {
            int j  = wn * 16 + ni * 4 + lc;   // h col within block (acc cols 2j,2j+1)
            int gj = nb + j;
            float bg = bg_base[gj];
            float bu = bu_base[gj];
            if (r < rowEnd) {
                float g = acc[mi][ni][0] + bg;
                float u = acc[mi][ni][1] + bu;
                g_h[(size_t)r * FFN_ + gj] = (g / (1.0f + expf(-g))) * u;
            }
            if (r + 8 < rowEnd) {
                float g = acc[mi][ni][2] + bg;
                float u = acc[mi][ni][3] + bu;
                g_h[(size_t)(r + 8) * FFN_ + gj] = (g / (1.0f + expf(-g))) * u;
            }
        }
    }
}

// ============================================================================
// GEMM2 (tf32 tensor cores): out[tok] += w * (h@W2^T + b2)
// Block tile: 128 rows x 128 cols. grid: (HID/128, 16, E), block 256
// ============================================================================
__global__ void __launch_bounds__(256)
k_gemm2(const float* __restrict__ w2,
        const float* __restrict__ w2b,
        float* __restrict__ out) {
    int e = blockIdx.z;
    int rowEnd = g_off[e + 1];
    int row0 = g_off[e] + blockIdx.y * BM;
    if (row0 >= rowEnd) return;
    int nb = blockIdx.x * 128;

    __shared__ float As[2][BM][LDS_];
    __shared__ float Bs[2][BM][LDS_];

    int tid  = threadIdx.x;
    int lane = tid & 31;
    int wid  = tid >> 5;
    int wm   = wid >> 2;
    int wn   = wid & 3;

    const float* aptr[2];
    const float* bptr[2];
    int ac4[2];
#pragma unroll
    for (int p = 0; p < 2; p++) {
        int idx = tid + 256 * p;
        int r   = idx >> 2;
        ac4[p]  = (idx & 3) * 4;
        int gr  = row0 + r;
        if (gr >= rowEnd) gr = rowEnd - 1;
        aptr[p] = g_h + (size_t)gr * FFN_;
        bptr[p] = w2 + ((size_t)e * HID_ + (nb + r)) * FFN_;
    }

    auto load_tile = [&](int buf, int k0) {
#pragma unroll
        for (int p = 0; p < 2; p++) {
            int idx = tid + 256 * p;
            int r   = idx >> 2;
            cpa16(&As[buf][r][ac4[p]], aptr[p] + k0 + ac4[p]);
            cpa16(&Bs[buf][r][ac4[p]], bptr[p] + k0 + ac4[p]);
        }
        cpa_commit();
    };

    float acc[4][4][4];
#pragma unroll
    for (int mi = 0; mi < 4; mi++)
#pragma unroll
        for (int ni = 0; ni < 4; ni++)
#pragma unroll
            for (int q = 0; q < 4; q++) acc[mi][ni][q] = 0.0f;

    const int NIT = FFN_ / BK;   // 128
    load_tile(0, 0);

    int lr = lane >> 2;
    int lc = lane & 3;

    for (int it = 0; it < NIT; it++) {
        int buf = it & 1;
        if (it + 1 < NIT) { load_tile(buf ^ 1, (it + 1) * BK); cpa_wait1(); }
        else              { cpa_wait0(); }
        __syncthreads();

#pragma unroll
        for (int s = 0; s < 2; s++) {
            int k0 = s * 8;
            uint32_t a[4][4], b[4][2];
#pragma unroll
            for (int mi = 0; mi < 4; mi++) {
                int r = wm * 64 + mi * 16 + lr;
                a[mi][0] = f2tf(As[buf][r][k0 + lc]);
                a[mi][1] = f2tf(As[buf][r + 8][k0 + lc]);
                a[mi][2] = f2tf(As[buf][r][k0 + lc + 4]);
                a[mi][3] = f2tf(As[buf][r + 8][k0 + lc + 4]);
            }
#pragma unroll
            for (int ni = 0; ni < 4; ni++) {
                int n = wn * 32 + ni * 8 + lr;
                b[ni][0] = f2tf(Bs[buf][n][k0 + lc]);
                b[ni][1] = f2tf(Bs[buf][n][k0 + lc + 4]);
            }
#pragma unroll
            for (int mi = 0; mi < 4; mi++)
#pragma unroll
                for (int ni = 0; ni < 4; ni++)
                    mma_tf32(acc[mi][ni], a[mi], b[ni], acc[mi][ni]);
        }
        __syncthreads();
    }

    // --- epilogue: bias, scale by combine weight, atomic-accumulate ---
    const float* b2 = w2b + (size_t)e * HID_;
#pragma unroll
    for (int mi = 0; mi < 4; mi++) {
        int r = row0 + wm * 64 + mi * 16 + lr;
#pragma unroll
        for (int ni = 0; ni < 4; ni++) {
            int c = nb + wn * 32 + ni * 8 + lc * 2;
            float b0 = b2[c], b1 = b2[c + 1];
            if (r < rowEnd) {
                int tok = g_tok[r]; float w = g_w[r];
                atomicAdd(&out[(size_t)tok * HID_ + c],     (acc[mi][ni][0] + b0) * w);
                atomicAdd(&out[(size_t)tok * HID_ + c + 1], (acc[mi][ni][1] + b1) * w);
            }
            if (r + 8 < rowEnd) {
                int tok = g_tok[r + 8]; float w = g_w[r + 8];
                atomicAdd(&out[(size_t)tok * HID_ + c],     (acc[mi][ni][2] + b0) * w);
                atomicAdd(&out[(size_t)tok * HID_ + c + 1], (acc[mi][ni][3] + b1) * w);
            }
        }
    }
}

// ---------------- launch ----------------
extern "C" void kernel_launch(void* const* d_in, const int* in_sizes, int n_in,
                              void* d_out, int out_size) {
    (void)in_sizes; (void)n_in; (void)out_size;
    const float* x   = (const float*)d_in[0];
    const float* rw  = (const float*)d_in[1];
    const float* rb  = (const float*)d_in[2];
    const float* w1  = (const float*)d_in[3];
    const float* w1b = (const float*)d_in[4];
    const float* w2  = (const float*)d_in[5];
    const float* w2b = (const float*)d_in[6];
    float* out = (float*)d_out;

    k_init<<<1024, 256>>>(out);
    k_router<<<M_TOK / 8, 256>>>(x, rw, rb, out);
    k_scan<<<1, 32>>>();
    k_place<<<NSLOT / 256, 256>>>();

    dim3 g1(FFN_ / 64, M_TOK / BM, E_);
    k_gemm1<<<g1, 256>>>(x, w1, w1b);

    dim3 g2(HID_ / 128, M_TOK / BM, E_);
    k_gemm2<<<g2, 256>>>(w2, w2b, out);
}

// round 5
// speedup vs baseline: 3.3212x; 1.1776x over previous
#include <cuda_runtime.h>
#include <cstdint>

#define E_       8
#define TOPK_    2
#define HID_     1024
#define FFN_     2048
#define M_TOK    2048
#define NSLOT    (M_TOK * TOPK_)      // 4096
#define OUT_MAIN (M_TOK * HID_)       // 2097152

#define BK    32
#define LDSW  36                      // padded smem row stride (floats)
#define ABUF  (128 * LDSW * 4)        // 18432 B per operand tile
#define STAGE (2 * ABUF)              // 36864 B per stage (A + B)

// ---------------- device scratch ----------------
__device__ int   g_cnt[E_];
__device__ int   g_off[E_ + 1];
__device__ int   g_cur[E_];
__device__ int   g_slot_e[NSLOT];
__device__ float g_slot_w[NSLOT];
__device__ int   g_tok[NSLOT];
__device__ float g_w[NSLOT];
__device__ float g_h[(size_t)NSLOT * FFN_];   // 32 MB (tf32-rounded)
__device__ float g_xr[(size_t)M_TOK * HID_];  // 8 MB  (tf32-rounded x)

// ---------------- helpers ----------------
__device__ __forceinline__ uint32_t f2tf(float f) {
    uint32_t r;
    asm("cvt.rna.tf32.f32 %0, %1;" : "=r"(r) : "f"(f));
    return r;
}
__device__ __forceinline__ float f_rna_tf32(float f) {
    return __uint_as_float(f2tf(f));
}
__device__ __forceinline__ void mma_tf32(float* d, const uint32_t* a,
                                         const uint32_t* b, const float* c) {
    asm volatile(
        "mma.sync.aligned.m16n8k8.row.col.f32.tf32.tf32.f32 "
        "{%0,%1,%2,%3}, {%4,%5,%6,%7}, {%8,%9}, {%10,%11,%12,%13};\n"
        : "=f"(d[0]), "=f"(d[1]), "=f"(d[2]), "=f"(d[3])
        : "r"(a[0]), "r"(a[1]), "r"(a[2]), "r"(a[3]),
          "r"(b[0]), "r"(b[1]),
          "f"(c[0]), "f"(c[1]), "f"(c[2]), "f"(c[3]));
}
__device__ __forceinline__ void cpa16(uint32_t saddr, const void* g) {
    asm volatile("cp.async.cg.shared.global [%0], [%1], 16;\n" :: "r"(saddr), "l"(g));
}
__device__ __forceinline__ void cpa_commit() { asm volatile("cp.async.commit_group;\n"); }
__device__ __forceinline__ void cpa_wait1()  { asm volatile("cp.async.wait_group 1;\n"); }
__device__ __forceinline__ void cpa_wait0()  { asm volatile("cp.async.wait_group 0;\n"); }
__device__ __forceinline__ uint32_t smem_u32(const void* p) {
    return (uint32_t)__cvta_generic_to_shared(p);
}

// ---------------- init / router / scan / place ----------------
__global__ void k_init(float* __restrict__ out) {
    int i = blockIdx.x * blockDim.x + threadIdx.x;
    if (i < E_) g_cnt[i] = 0;
    for (int j = i; j < OUT_MAIN; j += gridDim.x * blockDim.x) out[j] = 0.0f;
}

__global__ void k_router(const float* __restrict__ x,
                         const float* __restrict__ rw,
                         const float* __restrict__ rb,
                         float* __restrict__ out) {
    int warp = (blockIdx.x * blockDim.x + threadIdx.x) >> 5;
    int lane = threadIdx.x & 31;
    if (warp >= M_TOK) return;

    const float* xr = x + (size_t)warp * HID_;
    float xv[32];
#pragma unroll
    for (int i = 0; i < 32; i++) xv[i] = xr[lane + 32 * i];

    float logits[E_];
#pragma unroll
    for (int e = 0; e < E_; e++) {
        const float* w = rw + (size_t)e * HID_;
        float acc = 0.0f;
#pragma unroll
        for (int i = 0; i < 32; i++) acc += xv[i] * w[lane + 32 * i];
#pragma unroll
        for (int o = 16; o > 0; o >>= 1) acc += __shfl_xor_sync(0xffffffffu, acc, o);
        logits[e] = acc + rb[e];
    }

    if (lane == 0) {
        float mx = logits[0];
#pragma unroll
        for (int e = 1; e < E_; e++) mx = fmaxf(mx, logits[e]);
        float p[E_], s = 0.0f;
#pragma unroll
        for (int e = 0; e < E_; e++) { p[e] = expf(logits[e] - mx); s += p[e]; }
        float inv = 1.0f / s;
#pragma unroll
        for (int e = 0; e < E_; e++) p[e] *= inv;

        int i0 = 0;
#pragma unroll
        for (int e = 1; e < E_; e++) if (p[e] > p[i0]) i0 = e;
        int i1 = -1;
#pragma unroll
        for (int e = 0; e < E_; e++) {
            if (e == i0) continue;
            if (i1 < 0 || p[e] > p[i1]) i1 = e;
        }

        out[OUT_MAIN + warp * 2 + 0] = p[i0];
        out[OUT_MAIN + warp * 2 + 1] = p[i1];
        g_slot_e[warp * 2 + 0] = i0;  g_slot_w[warp * 2 + 0] = p[i0];
        g_slot_e[warp * 2 + 1] = i1;  g_slot_w[warp * 2 + 1] = p[i1];
        atomicAdd(&g_cnt[i0], 1);
        atomicAdd(&g_cnt[i1], 1);
    }
}

__global__ void k_scan() {
    if (threadIdx.x == 0) {
        int s = 0;
        for (int e = 0; e < E_; e++) { g_off[e] = s; g_cur[e] = s; s += g_cnt[e]; }
        g_off[E_] = s;
    }
}

__global__ void k_place() {
    int s = blockIdx.x * blockDim.x + threadIdx.x;
    if (s >= NSLOT) return;
    int e = g_slot_e[s];
    int p = atomicAdd(&g_cur[e], 1);
    g_tok[p] = s >> 1;
    g_w[p]   = g_slot_w[s];
}

// round x to tf32 (RNA) once
__global__ void k_cvt(const float4* __restrict__ src, float4* __restrict__ dst, int n4) {
    int i = blockIdx.x * blockDim.x + threadIdx.x;
    int stride = gridDim.x * blockDim.x;
    for (; i < n4; i += stride) {
        float4 v = src[i];
        v.x = f_rna_tf32(v.x); v.y = f_rna_tf32(v.y);
        v.z = f_rna_tf32(v.z); v.w = f_rna_tf32(v.w);
        dst[i] = v;
    }
}

// ============================================================================
// GEMM1: h = silu(x@Wg^T + bg) * (x@Wu^T + bu)
// Block: 128 slot rows x 64 h-cols (B tile = 128 interleaved gate/up rows).
// 256 threads = 8 warps (2m x 4n), warp tile 64x32. BK=32, 2-stage cp.async.
// ============================================================================
__global__ void __launch_bounds__(256, 2)
k_gemm1(const float* __restrict__ w1,
        const float* __restrict__ w1b) {
    int e = blockIdx.z;
    int rowEnd = g_off[e + 1];
    int row0 = g_off[e] + blockIdx.y * 128;
    if (row0 >= rowEnd) return;
    int nb = blockIdx.x * 64;

    extern __shared__ float dsm[];
    __shared__ const float* s_aptr[128];

    int tid  = threadIdx.x;
    int lane = tid & 31;
    int wid  = tid >> 5;
    int wm   = wid >> 2;
    int wn   = wid & 3;
    uint32_t sbase = smem_u32(dsm);

    for (int r = tid; r < 128; r += 256) {
        int gr = row0 + r;
        if (gr >= rowEnd) gr = rowEnd - 1;
        s_aptr[r] = g_xr + (size_t)g_tok[gr] * HID_;
    }
    __syncthreads();

    // per-thread load descriptors: 4 float4 each for A and B
    int rI[4], cI[4];
    const float* bp[4];
#pragma unroll
    for (int i = 0; i < 4; i++) {
        int idx = tid + 256 * i;
        rI[i] = idx >> 3;
        cI[i] = (idx & 7) * 4;
        int r = rI[i];
        size_t wrow = (size_t)e * 2 * FFN_ + ((r & 1) ? (FFN_ + nb + (r >> 1)) : (nb + (r >> 1)));
        bp[i] = w1 + wrow * HID_;
    }

    auto load_tile = [&](int s, int k0) {
        uint32_t st = sbase + s * STAGE;
#pragma unroll
        for (int i = 0; i < 4; i++) {
            uint32_t off = (uint32_t)(rI[i] * LDSW + cI[i]) * 4;
            cpa16(st + off,        s_aptr[rI[i]] + k0 + cI[i]);
            cpa16(st + ABUF + off, bp[i] + k0 + cI[i]);
        }
        cpa_commit();
    };

    float acc[4][4][4];
#pragma unroll
    for (int mi = 0; mi < 4; mi++)
#pragma unroll
        for (int ni = 0; ni < 4; ni++)
#pragma unroll
            for (int q = 0; q < 4; q++) acc[mi][ni][q] = 0.0f;

    const int NT = HID_ / BK;   // 32
    load_tile(0, 0);

    int lr = lane >> 2;
    int lc = lane & 3;

    for (int kt = 0; kt < NT; kt++) {
        int buf = kt & 1;
        if (kt + 1 < NT) { load_tile(buf ^ 1, (kt + 1) * BK); cpa_wait1(); }
        else             { cpa_wait0(); }
        __syncthreads();

        const float* At = dsm + (size_t)buf * (STAGE / 4);
        const float* Bt = At + ABUF / 4;
#pragma unroll
        for (int s = 0; s < 4; s++) {
            int k0 = s * 8;
            uint32_t a[4][4], b[4][2];
#pragma unroll
            for (int mi = 0; mi < 4; mi++) {
                int r = wm * 64 + mi * 16 + lr;
                a[mi][0] = __float_as_uint(At[r * LDSW + k0 + lc]);
                a[mi][1] = __float_as_uint(At[(r + 8) * LDSW + k0 + lc]);
                a[mi][2] = __float_as_uint(At[r * LDSW + k0 + lc + 4]);
                a[mi][3] = __float_as_uint(At[(r + 8) * LDSW + k0 + lc + 4]);
            }
#pragma unroll
            for (int ni = 0; ni < 4; ni++) {
                int n = wn * 32 + ni * 8 + lr;
                b[ni][0] = f2tf(Bt[n * LDSW + k0 + lc]);
                b[ni][1] = f2tf(Bt[n * LDSW + k0 + lc + 4]);
            }
#pragma unroll
            for (int mi = 0; mi < 4; mi++)
#pragma unroll
                for (int ni = 0; ni < 4; ni++)
                    mma_tf32(acc[mi][ni], a[mi], b[ni], acc[mi][ni]);
        }
        __syncthreads();
    }

    // epilogue: bias + silu*up, store tf32-rounded h
    const float* bg_base = w1b + (size_t)e * 2 * FFN_;
    const float* bu_base = bg_base + FFN_;
#pragma unroll
    for (int mi = 0; mi < 4; mi++) {
        int r = row0 + wm * 64 + mi * 16 + lr;
#pragma unroll
        for (int ni = 0; ni < 4; ni++) {
            int gj = nb + wn * 16 + ni * 4 + lc;
            float bg = bg_base[gj];
            float bu = bu_base[gj];
            if (r < rowEnd) {
                float g = acc[mi][ni][0] + bg;
                float u = acc[mi][ni][1] + bu;
                g_h[(size_t)r * FFN_ + gj] = f_rna_tf32((g / (1.0f + expf(-g))) * u);
            }
            if (r + 8 < rowEnd) {
                float g = acc[mi][ni][2] + bg;
                float u = acc[mi][ni][3] + bu;
                g_h[(size_t)(r + 8) * FFN_ + gj] = f_rna_tf32((g / (1.0f + expf(-g))) * u);
            }
        }
    }
}

// ============================================================================
// GEMM2: out[tok] += w * (h@W2^T + b2)
// Block: 128 slot rows x 128 out cols. 256 threads, warp 64x32. BK=32.
// ============================================================================
__global__ void __launch_bounds__(256, 2)
k_gemm2(const float* __restrict__ w2,
        const float* __restrict__ w2b,
        float* __restrict__ out) {
    int e = blockIdx.z;
    int rowEnd = g_off[e + 1];
    int row0 = g_off[e] + blockIdx.y * 128;
    if (row0 >= rowEnd) return;
    int nb = blockIdx.x * 128;

    extern __shared__ float dsm[];

    int tid  = threadIdx.x;
    int lane = tid & 31;
    int wid  = tid >> 5;
    int wm   = wid >> 2;
    int wn   = wid & 3;
    uint32_t sbase = smem_u32(dsm);

    int rI[4], cI[4];
    const float* ap[4];
    const float* bp[4];
#pragma unroll
    for (int i = 0; i < 4; i++) {
        int idx = tid + 256 * i;
        rI[i] = idx >> 3;
        cI[i] = (idx & 7) * 4;
        int gr = row0 + rI[i];
        if (gr >= rowEnd) gr = rowEnd - 1;
        ap[i] = g_h + (size_t)gr * FFN_;
        bp[i] = w2 + ((size_t)e * HID_ + (nb + rI[i])) * FFN_;
    }

    auto load_tile = [&](int s, int k0) {
        uint32_t st = sbase + s * STAGE;
#pragma unroll
        for (int i = 0; i < 4; i++) {
            uint32_t off = (uint32_t)(rI[i] * LDSW + cI[i]) * 4;
            cpa16(st + off,        ap[i] + k0 + cI[i]);
            cpa16(st + ABUF + off, bp[i] + k0 + cI[i]);
        }
        cpa_commit();
    };

    float acc[4][4][4];
#pragma unroll
    for (int mi = 0; mi < 4; mi++)
#pragma unroll
        for (int ni = 0; ni < 4; ni++)
#pragma unroll
            for (int q = 0; q < 4; q++) acc[mi][ni][q] = 0.0f;

    const int NT = FFN_ / BK;   // 64
    load_tile(0, 0);

    int lr = lane >> 2;
    int lc = lane & 3;

    for (int kt = 0; kt < NT; kt++) {
        int buf = kt & 1;
        if (kt + 1 < NT) { load_tile(buf ^ 1, (kt + 1) * BK); cpa_wait1(); }
        else             { cpa_wait0(); }
        __syncthreads();

        const float* At = dsm + (size_t)buf * (STAGE / 4);
        const float* Bt = At + ABUF / 4;
#pragma unroll
        for (int s = 0; s < 4; s++) {
            int k0 = s * 8;
            uint32_t a[4][4], b[4][2];
#pragma unroll
            for (int mi = 0; mi < 4; mi++) {
                int r = wm * 64 + mi * 16 + lr;
                a[mi][0] = __float_as_uint(At[r * LDSW + k0 + lc]);
                a[mi][1] = __float_as_uint(At[(r + 8) * LDSW + k0 + lc]);
                a[mi][2] = __float_as_uint(At[r * LDSW + k0 + lc + 4]);
                a[mi][3] = __float_as_uint(At[(r + 8) * LDSW + k0 + lc + 4]);
            }
#pragma unroll
            for (int ni = 0; ni < 4; ni++) {
                int n = wn * 32 + ni * 8 + lr;
                b[ni][0] = f2tf(Bt[n * LDSW + k0 + lc]);
                b[ni][1] = f2tf(Bt[n * LDSW + k0 + lc + 4]);
            }
#pragma unroll
            for (int mi = 0; mi < 4; mi++)
#pragma unroll
                for (int ni = 0; ni < 4; ni++)
                    mma_tf32(acc[mi][ni], a[mi], b[ni], acc[mi][ni]);
        }
        __syncthreads();
    }

    const float* b2 = w2b + (size_t)e * HID_;
#pragma unroll
    for (int mi = 0; mi < 4; mi++) {
        int r = row0 + wm * 64 + mi * 16 + lr;
#pragma unroll
        for (int ni = 0; ni < 4; ni++) {
            int c = nb + wn * 32 + ni * 8 + lc * 2;
            float b0 = b2[c], b1 = b2[c + 1];
            if (r < rowEnd) {
                int tok = g_tok[r]; float w = g_w[r];
                atomicAdd(&out[(size_t)tok * HID_ + c],     (acc[mi][ni][0] + b0) * w);
                atomicAdd(&out[(size_t)tok * HID_ + c + 1], (acc[mi][ni][1] + b1) * w);
            }
            if (r + 8 < rowEnd) {
                int tok = g_tok[r + 8]; float w = g_w[r + 8];
                atomicAdd(&out[(size_t)tok * HID_ + c],     (acc[mi][ni][2] + b0) * w);
                atomicAdd(&out[(size_t)tok * HID_ + c + 1], (acc[mi][ni][3] + b1) * w);
            }
        }
    }
}

// ---------------- launch ----------------
extern "C" void kernel_launch(void* const* d_in, const int* in_sizes, int n_in,
                              void* d_out, int out_size) {
    (void)in_sizes; (void)n_in; (void)out_size;
    const float* x   = (const float*)d_in[0];
    const float* rw  = (const float*)d_in[1];
    const float* rb  = (const float*)d_in[2];
    const float* w1  = (const float*)d_in[3];
    const float* w1b = (const float*)d_in[4];
    const float* w2  = (const float*)d_in[5];
    const float* w2b = (const float*)d_in[6];
    float* out = (float*)d_out;

    cudaFuncSetAttribute(k_gemm1, cudaFuncAttributeMaxDynamicSharedMemorySize, 2 * STAGE);
    cudaFuncSetAttribute(k_gemm2, cudaFuncAttributeMaxDynamicSharedMemorySize, 2 * STAGE);

    k_init<<<1024, 256>>>(out);
    k_router<<<M_TOK / 8, 256>>>(x, rw, rb, out);
    k_scan<<<1, 32>>>();
    k_place<<<NSLOT / 256, 256>>>();

    float* xr; cudaGetSymbolAddress((void**)&xr, g_xr);
    k_cvt<<<512, 256>>>((const float4*)x, (float4*)xr, (M_TOK * HID_) / 4);

    dim3 g1(FFN_ / 64, NSLOT / 128, E_);
    k_gemm1<<<g1, 256, 2 * STAGE>>>(w1, w1b);

    dim3 g2(HID_ / 128, NSLOT / 128, E_);
    k_gemm2<<<g2, 256, 2 * STAGE>>>(w2, w2b, out);
}

// round 6
// speedup vs baseline: 3.4131x; 1.0277x over previous
#include <cuda_runtime.h>
#include <cstdint>

#define E_       8
#define TOPK_    2
#define HID_     1024
#define FFN_     2048
#define M_TOK    2048
#define NSLOT    (M_TOK * TOPK_)      // 4096
#define OUT_MAIN (M_TOK * HID_)       // 2097152

#define BK    32
#define LDSW  36                      // padded smem row stride (floats)
#define ABUF  (128 * LDSW * 4)        // 18432 B per operand tile
#define STAGE (2 * ABUF)              // 36864 B per stage (A + B)
#define NSTG  3                       // pipeline stages (prefetch distance 2)

// ---------------- device scratch ----------------
__device__ int   g_cnt[E_];
__device__ int   g_off[E_ + 1];
__device__ int   g_cur[E_];
__device__ int   g_slot_e[NSLOT];
__device__ float g_slot_w[NSLOT];
__device__ int   g_tok[NSLOT];
__device__ float g_w[NSLOT];
__device__ float g_h[(size_t)NSLOT * FFN_];   // 32 MB (tf32-rounded)
__device__ float g_xr[(size_t)M_TOK * HID_];  // 8 MB  (tf32-rounded x)

// ---------------- helpers ----------------
__device__ __forceinline__ uint32_t f2tf(float f) {
    uint32_t r;
    asm("cvt.rna.tf32.f32 %0, %1;" : "=r"(r) : "f"(f));
    return r;
}
__device__ __forceinline__ float f_rna_tf32(float f) {
    return __uint_as_float(f2tf(f));
}
__device__ __forceinline__ void mma_tf32(float* d, const uint32_t* a,
                                         const uint32_t* b, const float* c) {
    asm volatile(
        "mma.sync.aligned.m16n8k8.row.col.f32.tf32.tf32.f32 "
        "{%0,%1,%2,%3}, {%4,%5,%6,%7}, {%8,%9}, {%10,%11,%12,%13};\n"
        : "=f"(d[0]), "=f"(d[1]), "=f"(d[2]), "=f"(d[3])
        : "r"(a[0]), "r"(a[1]), "r"(a[2]), "r"(a[3]),
          "r"(b[0]), "r"(b[1]),
          "f"(c[0]), "f"(c[1]), "f"(c[2]), "f"(c[3]));
}
__device__ __forceinline__ void cpa16(uint32_t saddr, const void* g) {
    asm volatile("cp.async.cg.shared.global [%0], [%1], 16;\n" :: "r"(saddr), "l"(g));
}
__device__ __forceinline__ void cpa_commit() { asm volatile("cp.async.commit_group;\n"); }
__device__ __forceinline__ void cpa_wait2()  { asm volatile("cp.async.wait_group 2;\n"); }
__device__ __forceinline__ void cpa_wait1()  { asm volatile("cp.async.wait_group 1;\n"); }
__device__ __forceinline__ void cpa_wait0()  { asm volatile("cp.async.wait_group 0;\n"); }
__device__ __forceinline__ uint32_t smem_u32(const void* p) {
    return (uint32_t)__cvta_generic_to_shared(p);
}

// ---------------- init / router / scan / place ----------------
__global__ void k_init(float* __restrict__ out) {
    int i = blockIdx.x * blockDim.x + threadIdx.x;
    if (i < E_) g_cnt[i] = 0;
    for (int j = i; j < OUT_MAIN; j += gridDim.x * blockDim.x) out[j] = 0.0f;
}

__global__ void k_router(const float* __restrict__ x,
                         const float* __restrict__ rw,
                         const float* __restrict__ rb,
                         float* __restrict__ out) {
    int warp = (blockIdx.x * blockDim.x + threadIdx.x) >> 5;
    int lane = threadIdx.x & 31;
    if (warp >= M_TOK) return;

    const float* xr = x + (size_t)warp * HID_;
    float xv[32];
#pragma unroll
    for (int i = 0; i < 32; i++) xv[i] = xr[lane + 32 * i];

    float logits[E_];
#pragma unroll
    for (int e = 0; e < E_; e++) {
        const float* w = rw + (size_t)e * HID_;
        float acc = 0.0f;
#pragma unroll
        for (int i = 0; i < 32; i++) acc += xv[i] * w[lane + 32 * i];
#pragma unroll
        for (int o = 16; o > 0; o >>= 1) acc += __shfl_xor_sync(0xffffffffu, acc, o);
        logits[e] = acc + rb[e];
    }

    if (lane == 0) {
        float mx = logits[0];
#pragma unroll
        for (int e = 1; e < E_; e++) mx = fmaxf(mx, logits[e]);
        float p[E_], s = 0.0f;
#pragma unroll
        for (int e = 0; e < E_; e++) { p[e] = expf(logits[e] - mx); s += p[e]; }
        float inv = 1.0f / s;
#pragma unroll
        for (int e = 0; e < E_; e++) p[e] *= inv;

        int i0 = 0;
#pragma unroll
        for (int e = 1; e < E_; e++) if (p[e] > p[i0]) i0 = e;
        int i1 = -1;
#pragma unroll
        for (int e = 0; e < E_; e++) {
            if (e == i0) continue;
            if (i1 < 0 || p[e] > p[i1]) i1 = e;
        }

        out[OUT_MAIN + warp * 2 + 0] = p[i0];
        out[OUT_MAIN + warp * 2 + 1] = p[i1];
        g_slot_e[warp * 2 + 0] = i0;  g_slot_w[warp * 2 + 0] = p[i0];
        g_slot_e[warp * 2 + 1] = i1;  g_slot_w[warp * 2 + 1] = p[i1];
        atomicAdd(&g_cnt[i0], 1);
        atomicAdd(&g_cnt[i1], 1);
    }
}

__global__ void k_scan() {
    if (threadIdx.x == 0) {
        int s = 0;
        for (int e = 0; e < E_; e++) { g_off[e] = s; g_cur[e] = s; s += g_cnt[e]; }
        g_off[E_] = s;
    }
}

__global__ void k_place() {
    int s = blockIdx.x * blockDim.x + threadIdx.x;
    if (s >= NSLOT) return;
    int e = g_slot_e[s];
    int p = atomicAdd(&g_cur[e], 1);
    g_tok[p] = s >> 1;
    g_w[p]   = g_slot_w[s];
}

// round x to tf32 (RNA) once
__global__ void k_cvt(const float4* __restrict__ src, float4* __restrict__ dst, int n4) {
    int i = blockIdx.x * blockDim.x + threadIdx.x;
    int stride = gridDim.x * blockDim.x;
    for (; i < n4; i += stride) {
        float4 v = src[i];
        v.x = f_rna_tf32(v.x); v.y = f_rna_tf32(v.y);
        v.z = f_rna_tf32(v.z); v.w = f_rna_tf32(v.w);
        dst[i] = v;
    }
}

// ============================================================================
// GEMM1: h = silu(x@Wg^T + bg) * (x@Wu^T + bu)
// Block: 128 slot rows x 64 h-cols. 256 threads (8 warps 2x4, warp 64x32).
// BK=32, 3-stage cp.async (prefetch distance 2).
// ============================================================================
__global__ void __launch_bounds__(256, 2)
k_gemm1(const float* __restrict__ w1,
        const float* __restrict__ w1b) {
    int e = blockIdx.z;
    int rowEnd = g_off[e + 1];
    int row0 = g_off[e] + blockIdx.y * 128;
    if (row0 >= rowEnd) return;
    int nb = blockIdx.x * 64;

    extern __shared__ float dsm[];
    __shared__ const float* s_aptr[128];

    int tid  = threadIdx.x;
    int lane = tid & 31;
    int wid  = tid >> 5;
    int wm   = wid >> 2;
    int wn   = wid & 3;
    uint32_t sbase = smem_u32(dsm);

    for (int r = tid; r < 128; r += 256) {
        int gr = row0 + r;
        if (gr >= rowEnd) gr = rowEnd - 1;
        s_aptr[r] = g_xr + (size_t)g_tok[gr] * HID_;
    }
    __syncthreads();

    int rI[4], cI[4];
    const float* bp[4];
#pragma unroll
    for (int i = 0; i < 4; i++) {
        int idx = tid + 256 * i;
        rI[i] = idx >> 3;
        cI[i] = (idx & 7) * 4;
        int r = rI[i];
        size_t wrow = (size_t)e * 2 * FFN_ + ((r & 1) ? (FFN_ + nb + (r >> 1)) : (nb + (r >> 1)));
        bp[i] = w1 + wrow * HID_;
    }

    auto load_tile = [&](int s, int k0) {
        uint32_t st = sbase + s * STAGE;
#pragma unroll
        for (int i = 0; i < 4; i++) {
            uint32_t off = (uint32_t)(rI[i] * LDSW + cI[i]) * 4;
            cpa16(st + off,        s_aptr[rI[i]] + k0 + cI[i]);
            cpa16(st + ABUF + off, bp[i] + k0 + cI[i]);
        }
        cpa_commit();
    };

    float acc[4][4][4];
#pragma unroll
    for (int mi = 0; mi < 4; mi++)
#pragma unroll
        for (int ni = 0; ni < 4; ni++)
#pragma unroll
            for (int q = 0; q < 4; q++) acc[mi][ni][q] = 0.0f;

    const int NT = HID_ / BK;   // 32
    load_tile(0, 0);
    load_tile(1, BK);

    int lr = lane >> 2;
    int lc = lane & 3;

    int buf = 0, nbuf = 2;
    for (int kt = 0; kt < NT; kt++) {
        if (kt + 2 < NT)      { load_tile(nbuf, (kt + 2) * BK); cpa_wait2(); }
        else if (kt + 1 < NT) { cpa_wait1(); }
        else                  { cpa_wait0(); }
        __syncthreads();

        const float* At = dsm + (size_t)buf * (STAGE / 4);
        const float* Bt = At + ABUF / 4;
#pragma unroll
        for (int s = 0; s < 4; s++) {
            int k0 = s * 8;
            uint32_t a[4][4], b[4][2];
#pragma unroll
            for (int mi = 0; mi < 4; mi++) {
                int r = wm * 64 + mi * 16 + lr;
                a[mi][0] = __float_as_uint(At[r * LDSW + k0 + lc]);
                a[mi][1] = __float_as_uint(At[(r + 8) * LDSW + k0 + lc]);
                a[mi][2] = __float_as_uint(At[r * LDSW + k0 + lc + 4]);
                a[mi][3] = __float_as_uint(At[(r + 8) * LDSW + k0 + lc + 4]);
            }
#pragma unroll
            for (int ni = 0; ni < 4; ni++) {
                int n = wn * 32 + ni * 8 + lr;
                b[ni][0] = f2tf(Bt[n * LDSW + k0 + lc]);
                b[ni][1] = f2tf(Bt[n * LDSW + k0 + lc + 4]);
            }
#pragma unroll
            for (int mi = 0; mi < 4; mi++)
#pragma unroll
                for (int ni = 0; ni < 4; ni++)
                    mma_tf32(acc[mi][ni], a[mi], b[ni], acc[mi][ni]);
        }
        __syncthreads();
        buf  = (buf  + 1) % NSTG;
        nbuf = (nbuf + 1) % NSTG;
    }

    // epilogue: bias + silu*up, store tf32-rounded h
    const float* bg_base = w1b + (size_t)e * 2 * FFN_;
    const float* bu_base = bg_base + FFN_;
#pragma unroll
    for (int mi = 0; mi < 4; mi++) {
        int r = row0 + wm * 64 + mi * 16 + lr;
#pragma unroll
        for (int ni = 0; ni < 4; ni++) {
            int gj = nb + wn * 16 + ni * 4 + lc;
            float bg = bg_base[gj];
            float bu = bu_base[gj];
            if (r < rowEnd) {
                float g = acc[mi][ni][0] + bg;
                float u = acc[mi][ni][1] + bu;
                g_h[(size_t)r * FFN_ + gj] = f_rna_tf32((g / (1.0f + expf(-g))) * u);
            }
            if (r + 8 < rowEnd) {
                float g = acc[mi][ni][2] + bg;
                float u = acc[mi][ni][3] + bu;
                g_h[(size_t)(r + 8) * FFN_ + gj] = f_rna_tf32((g / (1.0f + expf(-g))) * u);
            }
        }
    }
}

// ============================================================================
// GEMM2: out[tok] += w * (h@W2^T + b2)
// Block: 128 slot rows x 128 out cols. 256 threads, warp 64x32. BK=32, 3-stage.
// ============================================================================
__global__ void __launch_bounds__(256, 2)
k_gemm2(const float* __restrict__ w2,
        const float* __restrict__ w2b,
        float* __restrict__ out) {
    int e = blockIdx.z;
    int rowEnd = g_off[e + 1];
    int row0 = g_off[e] + blockIdx.y * 128;
    if (row0 >= rowEnd) return;
    int nb = blockIdx.x * 128;

    extern __shared__ float dsm[];

    int tid  = threadIdx.x;
    int lane = tid & 31;
    int wid  = tid >> 5;
    int wm   = wid >> 2;
    int wn   = wid & 3;
    uint32_t sbase = smem_u32(dsm);

    int rI[4], cI[4];
    const float* ap[4];
    const float* bp[4];
#pragma unroll
    for (int i = 0; i < 4; i++) {
        int idx = tid + 256 * i;
        rI[i] = idx >> 3;
        cI[i] = (idx & 7) * 4;
        int gr = row0 + rI[i];
        if (gr >= rowEnd) gr = rowEnd - 1;
        ap[i] = g_h + (size_t)gr * FFN_;
        bp[i] = w2 + ((size_t)e * HID_ + (nb + rI[i])) * FFN_;
    }

    auto load_tile = [&](int s, int k0) {
        uint32_t st = sbase + s * STAGE;
#pragma unroll
        for (int i = 0; i < 4; i++) {
            uint32_t off = (uint32_t)(rI[i] * LDSW + cI[i]) * 4;
            cpa16(st + off,        ap[i] + k0 + cI[i]);
            cpa16(st + ABUF + off, bp[i] + k0 + cI[i]);
        }
        cpa_commit();
    };

    float acc[4][4][4];
#pragma unroll
    for (int mi = 0; mi < 4; mi++)
#pragma unroll
        for (int ni = 0; ni < 4; ni++)
#pragma unroll
            for (int q = 0; q < 4; q++) acc[mi][ni][q] = 0.0f;

    const int NT = FFN_ / BK;   // 64
    load_tile(0, 0);
    load_tile(1, BK);

    int lr = lane >> 2;
    int lc = lane & 3;

    int buf = 0, nbuf = 2;
    for (int kt = 0; kt < NT; kt++) {
        if (kt + 2 < NT)      { load_tile(nbuf, (kt + 2) * BK); cpa_wait2(); }
        else if (kt + 1 < NT) { cpa_wait1(); }
        else                  { cpa_wait0(); }
        __syncthreads();

        const float* At = dsm + (size_t)buf * (STAGE / 4);
        const float* Bt = At + ABUF / 4;
#pragma unroll
        for (int s = 0; s < 4; s++) {
            int k0 = s * 8;
            uint32_t a[4][4], b[4][2];
#pragma unroll
            for (int mi = 0; mi < 4; mi++) {
                int r = wm * 64 + mi * 16 + lr;
                a[mi][0] = __float_as_uint(At[r * LDSW + k0 + lc]);
                a[mi][1] = __float_as_uint(At[(r + 8) * LDSW + k0 + lc]);
                a[mi][2] = __float_as_uint(At[r * LDSW + k0 + lc + 4]);
                a[mi][3] = __float_as_uint(At[(r + 8) * LDSW + k0 + lc + 4]);
            }
#pragma unroll
            for (int ni = 0; ni < 4; ni++) {
                int n = wn * 32 + ni * 8 + lr;
                b[ni][0] = f2tf(Bt[n * LDSW + k0 + lc]);
                b[ni][1] = f2tf(Bt[n * LDSW + k0 + lc + 4]);
            }
#pragma unroll
            for (int mi = 0; mi < 4; mi++)
#pragma unroll
                for (int ni = 0; ni < 4; ni++)
                    mma_tf32(acc[mi][ni], a[mi], b[ni], acc[mi][ni]);
        }
        __syncthreads();
        buf  = (buf  + 1) % NSTG;
        nbuf = (nbuf + 1) % NSTG;
    }

    const float* b2 = w2b + (size_t)e * HID_;
#pragma unroll
    for (int mi = 0; mi < 4; mi++) {
        int r = row0 + wm * 64 + mi * 16 + lr;
#pragma unroll
        for (int ni = 0; ni < 4; ni++) {
            int c = nb + wn * 32 + ni * 8 + lc * 2;
            float b0 = b2[c], b1 = b2[c + 1];
            if (r < rowEnd) {
                int tok = g_tok[r]; float w = g_w[r];
                atomicAdd(&out[(size_t)tok * HID_ + c],     (acc[mi][ni][0] + b0) * w);
                atomicAdd(&out[(size_t)tok * HID_ + c + 1], (acc[mi][ni][1] + b1) * w);
            }
            if (r + 8 < rowEnd) {
                int tok = g_tok[r + 8]; float w = g_w[r + 8];
                atomicAdd(&out[(size_t)tok * HID_ + c],     (acc[mi][ni][2] + b0) * w);
                atomicAdd(&out[(size_t)tok * HID_ + c + 1], (acc[mi][ni][3] + b1) * w);
            }
        }
    }
}

// ---------------- launch ----------------
extern "C" void kernel_launch(void* const* d_in, const int* in_sizes, int n_in,
                              void* d_out, int out_size) {
    (void)in_sizes; (void)n_in; (void)out_size;
    const float* x   = (const float*)d_in[0];
    const float* rw  = (const float*)d_in[1];
    const float* rb  = (const float*)d_in[2];
    const float* w1  = (const float*)d_in[3];
    const float* w1b = (const float*)d_in[4];
    const float* w2  = (const float*)d_in[5];
    const float* w2b = (const float*)d_in[6];
    float* out = (float*)d_out;

    cudaFuncSetAttribute(k_gemm1, cudaFuncAttributeMaxDynamicSharedMemorySize, NSTG * STAGE);
    cudaFuncSetAttribute(k_gemm2, cudaFuncAttributeMaxDynamicSharedMemorySize, NSTG * STAGE);

    k_init<<<1024, 256>>>(out);
    k_router<<<M_TOK / 8, 256>>>(x, rw, rb, out);
    k_scan<<<1, 32>>>();
    k_place<<<NSLOT / 256, 256>>>();

    float* xr; cudaGetSymbolAddress((void**)&xr, g_xr);
    k_cvt<<<512, 256>>>((const float4*)x, (float4*)xr, (M_TOK * HID_) / 4);

    dim3 g1(FFN_ / 64, NSLOT / 128, E_);
    k_gemm1<<<g1, 256, NSTG * STAGE>>>(w1, w1b);

    dim3 g2(HID_ / 128, NSLOT / 128, E_);
    k_gemm2<<<g2, 256, NSTG * STAGE>>>(w2, w2b, out);
}

// round 8
// speedup vs baseline: 4.1563x; 1.2177x over previous
#include <cuda_runtime.h>
#include <cuda_fp16.h>
#include <cstdint>

#define E_       8
#define TOPK_    2
#define HID_     1024
#define FFN_     2048
#define M_TOK    2048
#define NSLOT    (M_TOK * TOPK_)      // 4096
#define OUT_MAIN (M_TOK * HID_)       // 2097152

#define BK    32                      // k per tile (halves)
#define LDSW  40                      // padded smem row stride in halves (80B, 16B-aligned)
#define LDSW2 (LDSW / 2)              // row stride in uint32 units (20)
#define ABUF  (128 * LDSW * 2)        // 10240 B per operand tile
#define STAGE (2 * ABUF)              // 20480 B per stage (A + B)
#define NSTG  4                       // pipeline stages

// ---------------- device scratch ----------------
__device__ int    g_cnt[E_];
__device__ int    g_off[E_ + 1];
__device__ int    g_cur[E_];
__device__ int    g_slot_e[NSLOT];
__device__ float  g_slot_w[NSLOT];
__device__ int    g_tok[NSLOT];
__device__ float  g_w[NSLOT];
__device__ __half g_hh[(size_t)NSLOT * FFN_];            // 16 MB intermediate (fp16)
__device__ __half g_xh[(size_t)M_TOK * HID_];            // 4 MB x (fp16)
__device__ __half g_w1h[(size_t)E_ * 2 * FFN_ * HID_];   // 67 MB w1 (fp16)
__device__ __half g_w2h[(size_t)E_ * HID_ * FFN_];       // 34 MB w2 (fp16)

// ---------------- helpers ----------------
__device__ __forceinline__ void mma_f16(float* d, const uint32_t* a,
                                        const uint32_t* b, const float* c) {
    asm("mma.sync.aligned.m16n8k16.row.col.f32.f16.f16.f32 "
        "{%0,%1,%2,%3}, {%4,%5,%6,%7}, {%8,%9}, {%10,%11,%12,%13};\n"
        : "=f"(d[0]), "=f"(d[1]), "=f"(d[2]), "=f"(d[3])
        : "r"(a[0]), "r"(a[1]), "r"(a[2]), "r"(a[3]),
          "r"(b[0]), "r"(b[1]),
          "f"(c[0]), "f"(c[1]), "f"(c[2]), "f"(c[3]));
}
__device__ __forceinline__ void cpa16(uint32_t saddr, const void* g) {
    asm volatile("cp.async.cg.shared.global [%0], [%1], 16;\n" :: "r"(saddr), "l"(g));
}
__device__ __forceinline__ void cpa_commit() { asm volatile("cp.async.commit_group;\n"); }
__device__ __forceinline__ void cpa_wait3()  { asm volatile("cp.async.wait_group 3;\n"); }
__device__ __forceinline__ void cpa_wait2()  { asm volatile("cp.async.wait_group 2;\n"); }
__device__ __forceinline__ void cpa_wait1()  { asm volatile("cp.async.wait_group 1;\n"); }
__device__ __forceinline__ void cpa_wait0()  { asm volatile("cp.async.wait_group 0;\n"); }
__device__ __forceinline__ uint32_t smem_u32(const void* p) {
    return (uint32_t)__cvta_generic_to_shared(p);
}

// ---------------- init / router / scan / place ----------------
__global__ void k_init(float* __restrict__ out) {
    int i = blockIdx.x * blockDim.x + threadIdx.x;
    if (i < E_) g_cnt[i] = 0;
    for (int j = i; j < OUT_MAIN; j += gridDim.x * blockDim.x) out[j] = 0.0f;
}

__global__ void k_router(const float* __restrict__ x,
                         const float* __restrict__ rw,
                         const float* __restrict__ rb,
                         float* __restrict__ out) {
    int warp = (blockIdx.x * blockDim.x + threadIdx.x) >> 5;
    int lane = threadIdx.x & 31;
    if (warp >= M_TOK) return;

    const float* xr = x + (size_t)warp * HID_;
    float xv[32];
#pragma unroll
    for (int i = 0; i < 32; i++) xv[i] = xr[lane + 32 * i];

    float logits[E_];
#pragma unroll
    for (int e = 0; e < E_; e++) {
        const float* w = rw + (size_t)e * HID_;
        float acc = 0.0f;
#pragma unroll
        for (int i = 0; i < 32; i++) acc += xv[i] * w[lane + 32 * i];
#pragma unroll
        for (int o = 16; o > 0; o >>= 1) acc += __shfl_xor_sync(0xffffffffu, acc, o);
        logits[e] = acc + rb[e];
    }

    if (lane == 0) {
        float mx = logits[0];
#pragma unroll
        for (int e = 1; e < E_; e++) mx = fmaxf(mx, logits[e]);
        float p[E_], s = 0.0f;
#pragma unroll
        for (int e = 0; e < E_; e++) { p[e] = expf(logits[e] - mx); s += p[e]; }
        float inv = 1.0f / s;
#pragma unroll
        for (int e = 0; e < E_; e++) p[e] *= inv;

        int i0 = 0;
#pragma unroll
        for (int e = 1; e < E_; e++) if (p[e] > p[i0]) i0 = e;
        int i1 = -1;
#pragma unroll
        for (int e = 0; e < E_; e++) {
            if (e == i0) continue;
            if (i1 < 0 || p[e] > p[i1]) i1 = e;
        }

        out[OUT_MAIN + warp * 2 + 0] = p[i0];
        out[OUT_MAIN + warp * 2 + 1] = p[i1];
        g_slot_e[warp * 2 + 0] = i0;  g_slot_w[warp * 2 + 0] = p[i0];
        g_slot_e[warp * 2 + 1] = i1;  g_slot_w[warp * 2 + 1] = p[i1];
        atomicAdd(&g_cnt[i0], 1);
        atomicAdd(&g_cnt[i1], 1);
    }
}

__global__ void k_scan() {
    if (threadIdx.x == 0) {
        int s = 0;
        for (int e = 0; e < E_; e++) { g_off[e] = s; g_cur[e] = s; s += g_cnt[e]; }
        g_off[E_] = s;
    }
}

__global__ void k_place() {
    int s = blockIdx.x * blockDim.x + threadIdx.x;
    if (s >= NSLOT) return;
    int e = g_slot_e[s];
    int p = atomicAdd(&g_cur[e], 1);
    g_tok[p] = s >> 1;
    g_w[p]   = g_slot_w[s];
}

// fp32 -> fp16 streaming convert (RN)
__global__ void k_cvt_h(const float4* __restrict__ src, uint2* __restrict__ dst, int n4) {
    int i = blockIdx.x * blockDim.x + threadIdx.x;
    int stride = gridDim.x * blockDim.x;
    for (; i < n4; i += stride) {
        float4 v = src[i];
        __half2 lo = __floats2half2_rn(v.x, v.y);
        __half2 hi = __floats2half2_rn(v.z, v.w);
        uint2 o;
        o.x = *(uint32_t*)&lo;
        o.y = *(uint32_t*)&hi;
        dst[i] = o;
    }
}

// ============================================================================
// GEMM1 (fp16 HMMA m16n8k16): h = silu(x@Wg^T + bg) * (x@Wu^T + bu)
// Block: 128 slot rows x 64 h-cols (B = 128 interleaved gate/up rows).
// 256 threads = 8 warps (2m x 4n), warp tile 64x32. BK=32 halves, 4 stages.
// ============================================================================
__global__ void __launch_bounds__(256, 2)
k_gemm1(const float* __restrict__ w1b) {
    int e = blockIdx.z;
    int rowEnd = g_off[e + 1];
    int row0 = g_off[e] + blockIdx.y * 128;
    if (row0 >= rowEnd) return;
    int nb = blockIdx.x * 64;

    extern __shared__ __half dsm[];
    __shared__ const __half* s_aptr[128];

    int tid  = threadIdx.x;
    int lane = tid & 31;
    int wid  = tid >> 5;
    int wm   = wid >> 2;
    int wn   = wid & 3;
    uint32_t sbase = smem_u32(dsm);

    for (int r = tid; r < 128; r += 256) {
        int gr = row0 + r;
        if (gr >= rowEnd) gr = rowEnd - 1;
        s_aptr[r] = g_xh + (size_t)g_tok[gr] * HID_;
    }
    __syncthreads();

    // load descriptors: 2 granules of 16B per operand per thread
    int rI[2], cI[2];
    const __half* bp[2];
#pragma unroll
    for (int i = 0; i < 2; i++) {
        int idx = tid + 256 * i;
        rI[i] = idx >> 2;            // row 0..127
        cI[i] = (idx & 3) * 8;       // half offset 0,8,16,24
        int r = rI[i];
        size_t wrow = (size_t)e * 2 * FFN_ + ((r & 1) ? (FFN_ + nb + (r >> 1)) : (nb + (r >> 1)));
        bp[i] = g_w1h + wrow * HID_;
    }

    auto load_tile = [&](int s, int k0) {
        uint32_t st = sbase + s * STAGE;
#pragma unroll
        for (int i = 0; i < 2; i++) {
            uint32_t off = (uint32_t)(rI[i] * LDSW + cI[i]) * 2;
            cpa16(st + off,        s_aptr[rI[i]] + k0 + cI[i]);
            cpa16(st + ABUF + off, bp[i] + k0 + cI[i]);
        }
        cpa_commit();
    };

    float acc[4][4][4];
#pragma unroll
    for (int mi = 0; mi < 4; mi++)
#pragma unroll
        for (int ni = 0; ni < 4; ni++)
#pragma unroll
            for (int q = 0; q < 4; q++) acc[mi][ni][q] = 0.0f;

    const int NT = HID_ / BK;   // 32
    load_tile(0, 0);
    load_tile(1, BK);
    load_tile(2, 2 * BK);

    int lr = lane >> 2;
    int lc = lane & 3;

    for (int kt = 0; kt < NT; kt++) {
        int buf = kt & (NSTG - 1);
        if (kt + 3 < NT)      { load_tile((kt + 3) & (NSTG - 1), (kt + 3) * BK); cpa_wait3(); }
        else if (kt + 2 < NT) { cpa_wait2(); }
        else if (kt + 1 < NT) { cpa_wait1(); }
        else                  { cpa_wait0(); }
        __syncthreads();

        // view smem as half2 (uint32) units; row stride LDSW2 = 20
        const uint32_t* At = (const uint32_t*)(dsm + (size_t)buf * (STAGE / 2));
        const uint32_t* Bt = At + ABUF / 4;
#pragma unroll
        for (int s = 0; s < 2; s++) {          // two k16 substeps
            int k0 = s * 8;                    // half2 offset
            uint32_t a[4][4], b[4][2];
#pragma unroll
            for (int mi = 0; mi < 4; mi++) {
                int r = wm * 64 + mi * 16 + lr;
                a[mi][0] = At[r * LDSW2 + k0 + lc];
                a[mi][1] = At[(r + 8) * LDSW2 + k0 + lc];
                a[mi][2] = At[r * LDSW2 + k0 + lc + 4];
                a[mi][3] = At[(r + 8) * LDSW2 + k0 + lc + 4];
            }
#pragma unroll
            for (int ni = 0; ni < 4; ni++) {
                int n = wn * 32 + ni * 8 + lr;
                b[ni][0] = Bt[n * LDSW2 + k0 + lc];
                b[ni][1] = Bt[n * LDSW2 + k0 + lc + 4];
            }
#pragma unroll
            for (int mi = 0; mi < 4; mi++)
#pragma unroll
                for (int ni = 0; ni < 4; ni++)
                    mma_f16(acc[mi][ni], a[mi], b[ni], acc[mi][ni]);
        }
        __syncthreads();
    }

    // epilogue: bias + silu*up, store fp16 h
    const float* bg_base = w1b + (size_t)e * 2 * FFN_;
    const float* bu_base = bg_base + FFN_;
#pragma unroll
    for (int mi = 0; mi < 4; mi++) {
        int r = row0 + wm * 64 + mi * 16 + lr;
#pragma unroll
        for (int ni = 0; ni < 4; ni++) {
            int gj = nb + wn * 16 + ni * 4 + lc;
            float bg = bg_base[gj];
            float bu = bu_base[gj];
            if (r < rowEnd) {
                float g = acc[mi][ni][0] + bg;
                float u = acc[mi][ni][1] + bu;
                g_hh[(size_t)r * FFN_ + gj] = __float2half_rn((g / (1.0f + expf(-g))) * u);
            }
            if (r + 8 < rowEnd) {
                float g = acc[mi][ni][2] + bg;
                float u = acc[mi][ni][3] + bu;
                g_hh[(size_t)(r + 8) * FFN_ + gj] = __float2half_rn((g / (1.0f + expf(-g))) * u);
            }
        }
    }
}

// ============================================================================
// GEMM2 (fp16 HMMA): out[tok] += w * (h@W2^T + b2)
// Block: 128 slot rows x 128 out cols. 256 threads, warp 64x32. BK=32, 4 stages.
// ============================================================================
__global__ void __launch_bounds__(256, 2)
k_gemm2(const float* __restrict__ w2b, float* __restrict__ out) {
    int e = blockIdx.z;
    int rowEnd = g_off[e + 1];
    int row0 = g_off[e] + blockIdx.y * 128;
    if (row0 >= rowEnd) return;
    int nb = blockIdx.x * 128;

    extern __shared__ __half dsm[];

    int tid  = threadIdx.x;
    int lane = tid & 31;
    int wid  = tid >> 5;
    int wm   = wid >> 2;
    int wn   = wid & 3;
    uint32_t sbase = smem_u32(dsm);

    int rI[2], cI[2];
    const __half* ap[2];
    const __half* bp[2];
#pragma unroll
    for (int i = 0; i < 2; i++) {
        int idx = tid + 256 * i;
        rI[i] = idx >> 2;
        cI[i] = (idx & 3) * 8;
        int gr = row0 + rI[i];
        if (gr >= rowEnd) gr = rowEnd - 1;
        ap[i] = g_hh + (size_t)gr * FFN_;
        bp[i] = g_w2h + ((size_t)e * HID_ + (nb + rI[i])) * FFN_;
    }

    auto load_tile = [&](int s, int k0) {
        uint32_t st = sbase + s * STAGE;
#pragma unroll
        for (int i = 0; i < 2; i++) {
            uint32_t off = (uint32_t)(rI[i] * LDSW + cI[i]) * 2;
            cpa16(st + off,        ap[i] + k0 + cI[i]);
            cpa16(st + ABUF + off, bp[i] + k0 + cI[i]);
        }
        cpa_commit();
    };

    float acc[4][4][4];
#pragma unroll
    for (int mi = 0; mi < 4; mi++)
#pragma unroll
        for (int ni = 0; ni < 4; ni++)
#pragma unroll
            for (int q = 0; q < 4; q++) acc[mi][ni][q] = 0.0f;

    const int NT = FFN_ / BK;   // 64
    load_tile(0, 0);
    load_tile(1, BK);
    load_tile(2, 2 * BK);

    int lr = lane >> 2;
    int lc = lane & 3;

    for (int kt = 0; kt < NT; kt++) {
        int buf = kt & (NSTG - 1);
        if (kt + 3 < NT)      { load_tile((kt + 3) & (NSTG - 1), (kt + 3) * BK); cpa_wait3(); }
        else if (kt + 2 < NT) { cpa_wait2(); }
        else if (kt + 1 < NT) { cpa_wait1(); }
        else                  { cpa_wait0(); }
        __syncthreads();

        const uint32_t* At = (const uint32_t*)(dsm + (size_t)buf * (STAGE / 2));
        const uint32_t* Bt = At + ABUF / 4;
#pragma unroll
        for (int s = 0; s < 2; s++) {
            int k0 = s * 8;
            uint32_t a[4][4], b[4][2];
#pragma unroll
            for (int mi = 0; mi < 4; mi++) {
                int r = wm * 64 + mi * 16 + lr;
                a[mi][0] = At[r * LDSW2 + k0 + lc];
                a[mi][1] = At[(r + 8) * LDSW2 + k0 + lc];
                a[mi][2] = At[r * LDSW2 + k0 + lc + 4];
                a[mi][3] = At[(r + 8) * LDSW2 + k0 + lc + 4];
            }
#pragma unroll
            for (int ni = 0; ni < 4; ni++) {
                int n = wn * 32 + ni * 8 + lr;
                b[ni][0] = Bt[n * LDSW2 + k0 + lc];
                b[ni][1] = Bt[n * LDSW2 + k0 + lc + 4];
            }
#pragma unroll
            for (int mi = 0; mi < 4; mi++)
#pragma unroll
                for (int ni = 0; ni < 4; ni++)
                    mma_f16(acc[mi][ni], a[mi], b[ni], acc[mi][ni]);
        }
        __syncthreads();
    }

    const float* b2 = w2b + (size_t)e * HID_;
#pragma unroll
    for (int mi = 0; mi < 4; mi++) {
        int r = row0 + wm * 64 + mi * 16 + lr;
#pragma unroll
        for (int ni = 0; ni < 4; ni++) {
            int c = nb + wn * 32 + ni * 8 + lc * 2;
            float b0 = b2[c], b1 = b2[c + 1];
            if (r < rowEnd) {
                int tok = g_tok[r]; float w = g_w[r];
                atomicAdd(&out[(size_t)tok * HID_ + c],     (acc[mi][ni][0] + b0) * w);
                atomicAdd(&out[(size_t)tok * HID_ + c + 1], (acc[mi][ni][1] + b1) * w);
            }
            if (r + 8 < rowEnd) {
                int tok = g_tok[r + 8]; float w = g_w[r + 8];
                atomicAdd(&out[(size_t)tok * HID_ + c],     (acc[mi][ni][2] + b0) * w);
                atomicAdd(&out[(size_t)tok * HID_ + c + 1], (acc[mi][ni][3] + b1) * w);
            }
        }
    }
}

// ---------------- launch ----------------
extern "C" void kernel_launch(void* const* d_in, const int* in_sizes, int n_in,
                              void* d_out, int out_size) {
    (void)in_sizes; (void)n_in; (void)out_size;
    const float* x   = (const float*)d_in[0];
    const float* rw  = (const float*)d_in[1];
    const float* rb  = (const float*)d_in[2];
    const float* w1  = (const float*)d_in[3];
    const float* w1b = (const float*)d_in[4];
    const float* w2  = (const float*)d_in[5];
    const float* w2b = (const float*)d_in[6];
    float* out = (float*)d_out;

    cudaFuncSetAttribute(k_gemm1, cudaFuncAttributeMaxDynamicSharedMemorySize, NSTG * STAGE);
    cudaFuncSetAttribute(k_gemm2, cudaFuncAttributeMaxDynamicSharedMemorySize, NSTG * STAGE);

    k_init<<<1024, 256>>>(out);
    k_router<<<M_TOK / 8, 256>>>(x, rw, rb, out);
    k_scan<<<1, 32>>>();
    k_place<<<NSLOT / 256, 256>>>();

    __half* xh;  cudaGetSymbolAddress((void**)&xh,  g_xh);
    __half* w1h; cudaGetSymbolAddress((void**)&w1h, g_w1h);
    __half* w2h; cudaGetSymbolAddress((void**)&w2h, g_w2h);
    k_cvt_h<<<512, 256>>>((const float4*)x,  (uint2*)xh,  (M_TOK * HID_) / 4);
    k_cvt_h<<<2048, 256>>>((const float4*)w1, (uint2*)w1h, (E_ * 2 * FFN_ * HID_) / 4);
    k_cvt_h<<<2048, 256>>>((const float4*)w2, (uint2*)w2h, (E_ * HID_ * FFN_) / 4);

    dim3 g1(FFN_ / 64, NSLOT / 128, E_);
    k_gemm1<<<g1, 256, NSTG * STAGE>>>(w1b);

    dim3 g2(HID_ / 128, NSLOT / 128, E_);
    k_gemm2<<<g2, 256, NSTG * STAGE>>>(w2b, out);
}

// round 9
// speedup vs baseline: 4.3044x; 1.0356x over previous
#include <cuda_runtime.h>
#include <cuda_fp16.h>
#include <cstdint>

#define E_       8
#define TOPK_    2
#define HID_     1024
#define FFN_     2048
#define M_TOK    2048
#define NSLOT    (M_TOK * TOPK_)      // 4096
#define OUT_MAIN (M_TOK * HID_)       // 2097152

#define BK    32                      // k per tile (halves)
#define LDSW  40                      // padded smem row stride in halves (80B, 16B-aligned)
#define ROWB  80                      // row stride in bytes
#define ABUF  (128 * ROWB)            // 10240 B per operand tile
#define STAGE (2 * ABUF)              // 20480 B per stage (A + B)
#define NSTG  4                       // pipeline stages

// ---------------- device scratch ----------------
__device__ int    g_cnt[E_];
__device__ int    g_off[E_ + 1];
__device__ int    g_cur[E_];
__device__ int    g_slot_e[NSLOT];
__device__ float  g_slot_w[NSLOT];
__device__ int    g_tok[NSLOT];
__device__ float  g_w[NSLOT];
__device__ __half g_hh[(size_t)NSLOT * FFN_];            // 16 MB intermediate (fp16)
__device__ __half g_xh[(size_t)M_TOK * HID_];            // 4 MB x (fp16)
__device__ __half g_w1h[(size_t)E_ * 2 * FFN_ * HID_];   // 67 MB w1 (fp16)
__device__ __half g_w2h[(size_t)E_ * HID_ * FFN_];       // 34 MB w2 (fp16)

// ---------------- helpers ----------------
__device__ __forceinline__ void mma_f16(float* d, const uint32_t* a,
                                        const uint32_t* b, const float* c) {
    asm("mma.sync.aligned.m16n8k16.row.col.f32.f16.f16.f32 "
        "{%0,%1,%2,%3}, {%4,%5,%6,%7}, {%8,%9}, {%10,%11,%12,%13};\n"
        : "=f"(d[0]), "=f"(d[1]), "=f"(d[2]), "=f"(d[3])
        : "r"(a[0]), "r"(a[1]), "r"(a[2]), "r"(a[3]),
          "r"(b[0]), "r"(b[1]),
          "f"(c[0]), "f"(c[1]), "f"(c[2]), "f"(c[3]));
}
__device__ __forceinline__ void ldsm_x4(uint32_t& r0, uint32_t& r1,
                                        uint32_t& r2, uint32_t& r3, uint32_t addr) {
    asm volatile("ldmatrix.sync.aligned.m8n8.x4.shared.b16 {%0,%1,%2,%3}, [%4];"
                 : "=r"(r0), "=r"(r1), "=r"(r2), "=r"(r3) : "r"(addr));
}
__device__ __forceinline__ void cpa16(uint32_t saddr, const void* g) {
    asm volatile("cp.async.cg.shared.global [%0], [%1], 16;\n" :: "r"(saddr), "l"(g));
}
__device__ __forceinline__ void cpa_commit() { asm volatile("cp.async.commit_group;\n"); }
__device__ __forceinline__ void cpa_wait3()  { asm volatile("cp.async.wait_group 3;\n"); }
__device__ __forceinline__ void cpa_wait2()  { asm volatile("cp.async.wait_group 2;\n"); }
__device__ __forceinline__ void cpa_wait1()  { asm volatile("cp.async.wait_group 1;\n"); }
__device__ __forceinline__ void cpa_wait0()  { asm volatile("cp.async.wait_group 0;\n"); }
__device__ __forceinline__ uint32_t smem_u32(const void* p) {
    return (uint32_t)__cvta_generic_to_shared(p);
}

// ---------------- init / router / scan / place ----------------
__global__ void k_init(float* __restrict__ out) {
    int i = blockIdx.x * blockDim.x + threadIdx.x;
    if (i < E_) g_cnt[i] = 0;
    for (int j = i; j < OUT_MAIN; j += gridDim.x * blockDim.x) out[j] = 0.0f;
}

__global__ void k_router(const float* __restrict__ x,
                         const float* __restrict__ rw,
                         const float* __restrict__ rb,
                         float* __restrict__ out) {
    int warp = (blockIdx.x * blockDim.x + threadIdx.x) >> 5;
    int lane = threadIdx.x & 31;
    if (warp >= M_TOK) return;

    const float* xr = x + (size_t)warp * HID_;
    float xv[32];
#pragma unroll
    for (int i = 0; i < 32; i++) xv[i] = xr[lane + 32 * i];

    float logits[E_];
#pragma unroll
    for (int e = 0; e < E_; e++) {
        const float* w = rw + (size_t)e * HID_;
        float acc = 0.0f;
#pragma unroll
        for (int i = 0; i < 32; i++) acc += xv[i] * w[lane + 32 * i];
#pragma unroll
        for (int o = 16; o > 0; o >>= 1) acc += __shfl_xor_sync(0xffffffffu, acc, o);
        logits[e] = acc + rb[e];
    }

    if (lane == 0) {
        float mx = logits[0];
#pragma unroll
        for (int e = 1; e < E_; e++) mx = fmaxf(mx, logits[e]);
        float p[E_], s = 0.0f;
#pragma unroll
        for (int e = 0; e < E_; e++) { p[e] = expf(logits[e] - mx); s += p[e]; }
        float inv = 1.0f / s;
#pragma unroll
        for (int e = 0; e < E_; e++) p[e] *= inv;

        int i0 = 0;
#pragma unroll
        for (int e = 1; e < E_; e++) if (p[e] > p[i0]) i0 = e;
        int i1 = -1;
#pragma unroll
        for (int e = 0; e < E_; e++) {
            if (e == i0) continue;
            if (i1 < 0 || p[e] > p[i1]) i1 = e;
        }

        out[OUT_MAIN + warp * 2 + 0] = p[i0];
        out[OUT_MAIN + warp * 2 + 1] = p[i1];
        g_slot_e[warp * 2 + 0] = i0;  g_slot_w[warp * 2 + 0] = p[i0];
        g_slot_e[warp * 2 + 1] = i1;  g_slot_w[warp * 2 + 1] = p[i1];
        atomicAdd(&g_cnt[i0], 1);
        atomicAdd(&g_cnt[i1], 1);
    }
}

__global__ void k_scan() {
    if (threadIdx.x == 0) {
        int s = 0;
        for (int e = 0; e < E_; e++) { g_off[e] = s; g_cur[e] = s; s += g_cnt[e]; }
        g_off[E_] = s;
    }
}

__global__ void k_place() {
    int s = blockIdx.x * blockDim.x + threadIdx.x;
    if (s >= NSLOT) return;
    int e = g_slot_e[s];
    int p = atomicAdd(&g_cur[e], 1);
    g_tok[p] = s >> 1;
    g_w[p]   = g_slot_w[s];
}

// fp32 -> fp16 streaming convert (RN)
__global__ void k_cvt_h(const float4* __restrict__ src, uint2* __restrict__ dst, int n4) {
    int i = blockIdx.x * blockDim.x + threadIdx.x;
    int stride = gridDim.x * blockDim.x;
    for (; i < n4; i += stride) {
        float4 v = src[i];
        __half2 lo = __floats2half2_rn(v.x, v.y);
        __half2 hi = __floats2half2_rn(v.z, v.w);
        uint2 o;
        o.x = *(uint32_t*)&lo;
        o.y = *(uint32_t*)&hi;
        dst[i] = o;
    }
}

// ============================================================================
// GEMM1 (fp16 HMMA + ldmatrix): h = silu(x@Wg^T + bg) * (x@Wu^T + bu)
// Block: 128 slot rows x 64 h-cols (B = 128 interleaved gate/up rows).
// 256 threads = 8 warps (2m x 4n), warp tile 64x32. BK=32 halves, 4 stages.
// ============================================================================
__global__ void __launch_bounds__(256, 2)
k_gemm1(const float* __restrict__ w1b) {
    int e = blockIdx.z;
    int rowEnd = g_off[e + 1];
    int row0 = g_off[e] + blockIdx.y * 128;
    if (row0 >= rowEnd) return;
    int nb = blockIdx.x * 64;

    extern __shared__ __half dsm[];
    __shared__ const __half* s_aptr[128];

    int tid  = threadIdx.x;
    int lane = tid & 31;
    int wid  = tid >> 5;
    int wm   = wid >> 2;
    int wn   = wid & 3;
    uint32_t sbase = smem_u32(dsm);

    for (int r = tid; r < 128; r += 256) {
        int gr = row0 + r;
        if (gr >= rowEnd) gr = rowEnd - 1;
        s_aptr[r] = g_xh + (size_t)g_tok[gr] * HID_;
    }
    __syncthreads();

    // cp.async load descriptors: 2 granules of 16B per operand per thread
    int rI[2], cI[2];
    const __half* bp[2];
#pragma unroll
    for (int i = 0; i < 2; i++) {
        int idx = tid + 256 * i;
        rI[i] = idx >> 2;            // row 0..127
        cI[i] = (idx & 3) * 8;       // half offset 0,8,16,24
        int r = rI[i];
        size_t wrow = (size_t)e * 2 * FFN_ + ((r & 1) ? (FFN_ + nb + (r >> 1)) : (nb + (r >> 1)));
        bp[i] = g_w1h + wrow * HID_;
    }

    auto load_tile = [&](int s, int k0) {
        uint32_t st = sbase + s * STAGE;
#pragma unroll
        for (int i = 0; i < 2; i++) {
            uint32_t off = (uint32_t)(rI[i] * LDSW + cI[i]) * 2;
            cpa16(st + off,        s_aptr[rI[i]] + k0 + cI[i]);
            cpa16(st + ABUF + off, bp[i] + k0 + cI[i]);
        }
        cpa_commit();
    };

    float acc[4][4][4];
#pragma unroll
    for (int mi = 0; mi < 4; mi++)
#pragma unroll
        for (int ni = 0; ni < 4; ni++)
#pragma unroll
            for (int q = 0; q < 4; q++) acc[mi][ni][q] = 0.0f;

    const int NT = HID_ / BK;   // 32
    load_tile(0, 0);
    load_tile(1, BK);
    load_tile(2, 2 * BK);

    int lr = lane >> 2;
    int lc = lane & 3;

    // ldmatrix per-lane row offsets
    uint32_t a_loff = (uint32_t)((lane & 15) * ROWB + ((lane >> 4) & 1) * 16)
                    + (uint32_t)(wm * 64 * ROWB);
    uint32_t b_loff = (uint32_t)((((lane >> 4) & 1) * 8 + (lane & 7)) * ROWB
                    + ((lane >> 3) & 1) * 16)
                    + (uint32_t)(wn * 32 * ROWB);

    for (int kt = 0; kt < NT; kt++) {
        int buf = kt & (NSTG - 1);
        if (kt + 3 < NT)      { load_tile((kt + 3) & (NSTG - 1), (kt + 3) * BK); cpa_wait3(); }
        else if (kt + 2 < NT) { cpa_wait2(); }
        else if (kt + 1 < NT) { cpa_wait1(); }
        else                  { cpa_wait0(); }
        __syncthreads();

        uint32_t At = sbase + buf * STAGE;
        uint32_t Bt = At + ABUF;
#pragma unroll
        for (int s = 0; s < 2; s++) {          // two k16 substeps
            uint32_t ks = s * 32;              // byte offset along k
            uint32_t a[4][4], b[4][2];
#pragma unroll
            for (int mi = 0; mi < 4; mi++)
                ldsm_x4(a[mi][0], a[mi][1], a[mi][2], a[mi][3],
                        At + (uint32_t)(mi * 16 * ROWB) + ks + a_loff);
#pragma unroll
            for (int nj = 0; nj < 2; nj++)
                ldsm_x4(b[2 * nj][0], b[2 * nj][1], b[2 * nj + 1][0], b[2 * nj + 1][1],
                        Bt + (uint32_t)(nj * 16 * ROWB) + ks + b_loff);
#pragma unroll
            for (int mi = 0; mi < 4; mi++)
#pragma unroll
                for (int ni = 0; ni < 4; ni++)
                    mma_f16(acc[mi][ni], a[mi], b[ni], acc[mi][ni]);
        }
        __syncthreads();
    }

    // epilogue: bias + silu*up, store fp16 h
    const float* bg_base = w1b + (size_t)e * 2 * FFN_;
    const float* bu_base = bg_base + FFN_;
#pragma unroll
    for (int mi = 0; mi < 4; mi++) {
        int r = row0 + wm * 64 + mi * 16 + lr;
#pragma unroll
        for (int ni = 0; ni < 4; ni++) {
            int gj = nb + wn * 16 + ni * 4 + lc;
            float bg = bg_base[gj];
            float bu = bu_base[gj];
            if (r < rowEnd) {
                float g = acc[mi][ni][0] + bg;
                float u = acc[mi][ni][1] + bu;
                g_hh[(size_t)r * FFN_ + gj] = __float2half_rn((g / (1.0f + expf(-g))) * u);
            }
            if (r + 8 < rowEnd) {
                float g = acc[mi][ni][2] + bg;
                float u = acc[mi][ni][3] + bu;
                g_hh[(size_t)(r + 8) * FFN_ + gj] = __float2half_rn((g / (1.0f + expf(-g))) * u);
            }
        }
    }
}

// ============================================================================
// GEMM2 (fp16 HMMA + ldmatrix): out[tok] += w * (h@W2^T + b2)
// Block: 128 slot rows x 128 out cols. 256 threads, warp 64x32. BK=32, 4 stages.
// ============================================================================
__global__ void __launch_bounds__(256, 2)
k_gemm2(const float* __restrict__ w2b, float* __restrict__ out) {
    int e = blockIdx.z;
    int rowEnd = g_off[e + 1];
    int row0 = g_off[e] + blockIdx.y * 128;
    if (row0 >= rowEnd) return;
    int nb = blockIdx.x * 128;

    extern __shared__ __half dsm[];

    int tid  = threadIdx.x;
    int lane = tid & 31;
    int wid  = tid >> 5;
    int wm   = wid >> 2;
    int wn   = wid & 3;
    uint32_t sbase = smem_u32(dsm);

    int rI[2], cI[2];
    const __half* ap[2];
    const __half* bp[2];
#pragma unroll
    for (int i = 0; i < 2; i++) {
        int idx = tid + 256 * i;
        rI[i] = idx >> 2;
        cI[i] = (idx & 3) * 8;
        int gr = row0 + rI[i];
        if (gr >= rowEnd) gr = rowEnd - 1;
        ap[i] = g_hh + (size_t)gr * FFN_;
        bp[i] = g_w2h + ((size_t)e * HID_ + (nb + rI[i])) * FFN_;
    }

    auto load_tile = [&](int s, int k0) {
        uint32_t st = sbase + s * STAGE;
#pragma unroll
        for (int i = 0; i < 2; i++) {
            uint32_t off = (uint32_t)(rI[i] * LDSW + cI[i]) * 2;
            cpa16(st + off,        ap[i] + k0 + cI[i]);
            cpa16(st + ABUF + off, bp[i] + k0 + cI[i]);
        }
        cpa_commit();
    };

    float acc[4][4][4];
#pragma unroll
    for (int mi = 0; mi < 4; mi++)
#pragma unroll
        for (int ni = 0; ni < 4; ni++)
#pragma unroll
            for (int q = 0; q < 4; q++) acc[mi][ni][q] = 0.0f;

    const int NT = FFN_ / BK;   // 64
    load_tile(0, 0);
    load_tile(1, BK);
    load_tile(2, 2 * BK);

    int lr = lane >> 2;
    int lc = lane & 3;

    uint32_t a_loff = (uint32_t)((lane & 15) * ROWB + ((lane >> 4) & 1) * 16)
                    + (uint32_t)(wm * 64 * ROWB);
    uint32_t b_loff = (uint32_t)((((lane >> 4) & 1) * 8 + (lane & 7)) * ROWB
                    + ((lane >> 3) & 1) * 16)
                    + (uint32_t)(wn * 32 * ROWB);

    for (int kt = 0; kt < NT; kt++) {
        int buf = kt & (NSTG - 1);
        if (kt + 3 < NT)      { load_tile((kt + 3) & (NSTG - 1), (kt + 3) * BK); cpa_wait3(); }
        else if (kt + 2 < NT) { cpa_wait2(); }
        else if (kt + 1 < NT) { cpa_wait1(); }
        else                  { cpa_wait0(); }
        __syncthreads();

        uint32_t At = sbase + buf * STAGE;
        uint32_t Bt = At + ABUF;
#pragma unroll
        for (int s = 0; s < 2; s++) {
            uint32_t ks = s * 32;
            uint32_t a[4][4], b[4][2];
#pragma unroll
            for (int mi = 0; mi < 4; mi++)
                ldsm_x4(a[mi][0], a[mi][1], a[mi][2], a[mi][3],
                        At + (uint32_t)(mi * 16 * ROWB) + ks + a_loff);
#pragma unroll
            for (int nj = 0; nj < 2; nj++)
                ldsm_x4(b[2 * nj][0], b[2 * nj][1], b[2 * nj + 1][0], b[2 * nj + 1][1],
                        Bt + (uint32_t)(nj * 16 * ROWB) + ks + b_loff);
#pragma unroll
            for (int mi = 0; mi < 4; mi++)
#pragma unroll
                for (int ni = 0; ni < 4; ni++)
                    mma_f16(acc[mi][ni], a[mi], b[ni], acc[mi][ni]);
        }
        __syncthreads();
    }

    const float* b2 = w2b + (size_t)e * HID_;
#pragma unroll
    for (int mi = 0; mi < 4; mi++) {
        int r = row0 + wm * 64 + mi * 16 + lr;
#pragma unroll
        for (int ni = 0; ni < 4; ni++) {
            int c = nb + wn * 32 + ni * 8 + lc * 2;
            float b0 = b2[c], b1 = b2[c + 1];
            if (r < rowEnd) {
                int tok = g_tok[r]; float w = g_w[r];
                atomicAdd(&out[(size_t)tok * HID_ + c],     (acc[mi][ni][0] + b0) * w);
                atomicAdd(&out[(size_t)tok * HID_ + c + 1], (acc[mi][ni][1] + b1) * w);
            }
            if (r + 8 < rowEnd) {
                int tok = g_tok[r + 8]; float w = g_w[r + 8];
                atomicAdd(&out[(size_t)tok * HID_ + c],     (acc[mi][ni][2] + b0) * w);
                atomicAdd(&out[(size_t)tok * HID_ + c + 1], (acc[mi][ni][3] + b1) * w);
            }
        }
    }
}

// ---------------- launch ----------------
extern "C" void kernel_launch(void* const* d_in, const int* in_sizes, int n_in,
                              void* d_out, int out_size) {
    (void)in_sizes; (void)n_in; (void)out_size;
    const float* x   = (const float*)d_in[0];
    const float* rw  = (const float*)d_in[1];
    const float* rb  = (const float*)d_in[2];
    const float* w1  = (const float*)d_in[3];
    const float* w1b = (const float*)d_in[4];
    const float* w2  = (const float*)d_in[5];
    const float* w2b = (const float*)d_in[6];
    float* out = (float*)d_out;

    cudaFuncSetAttribute(k_gemm1, cudaFuncAttributeMaxDynamicSharedMemorySize, NSTG * STAGE);
    cudaFuncSetAttribute(k_gemm2, cudaFuncAttributeMaxDynamicSharedMemorySize, NSTG * STAGE);

    k_init<<<1024, 256>>>(out);
    k_router<<<M_TOK / 8, 256>>>(x, rw, rb, out);
    k_scan<<<1, 32>>>();
    k_place<<<NSLOT / 256, 256>>>();

    __half* xh;  cudaGetSymbolAddress((void**)&xh,  g_xh);
    __half* w1h; cudaGetSymbolAddress((void**)&w1h, g_w1h);
    __half* w2h; cudaGetSymbolAddress((void**)&w2h, g_w2h);
    k_cvt_h<<<512, 256>>>((const float4*)x,  (uint2*)xh,  (M_TOK * HID_) / 4);
    k_cvt_h<<<2048, 256>>>((const float4*)w1, (uint2*)w1h, (E_ * 2 * FFN_ * HID_) / 4);
    k_cvt_h<<<2048, 256>>>((const float4*)w2, (uint2*)w2h, (E_ * HID_ * FFN_) / 4);

    dim3 g1(FFN_ / 64, NSLOT / 128, E_);
    k_gemm1<<<g1, 256, NSTG * STAGE>>>(w1b);

    dim3 g2(HID_ / 128, NSLOT / 128, E_);
    k_gemm2<<<g2, 256, NSTG * STAGE>>>(w2b, out);
}

// round 10
// speedup vs baseline: 4.4507x; 1.0340x over previous
#include <cuda_runtime.h>
#include <cuda_fp16.h>
#include <cstdint>

#define E_       8
#define TOPK_    2
#define HID_     1024
#define FFN_     2048
#define M_TOK    2048
#define NSLOT    (M_TOK * TOPK_)      // 4096
#define OUT_MAIN (M_TOK * HID_)       // 2097152

#define BK    32                      // k per tile (halves)
#define LDSW  40                      // padded smem row stride in halves (80B, 16B-aligned)
#define ROWB  80                      // row stride in bytes
#define ABUF  (128 * ROWB)            // 10240 B per operand tile
#define STAGE (2 * ABUF)              // 20480 B per stage (A + B)
#define NSTG  4                       // pipeline stages

// ---------------- device scratch ----------------
__device__ int    g_cnt[E_];
__device__ int    g_off[E_ + 1];
__device__ int    g_cur[E_];
__device__ int    g_slot_e[NSLOT];
__device__ float  g_slot_w[NSLOT];
__device__ int    g_tok[NSLOT];
__device__ float  g_w[NSLOT];
__device__ __half g_hh[(size_t)NSLOT * FFN_];            // 16 MB intermediate (fp16)
__device__ __half g_xh[(size_t)M_TOK * HID_];            // 4 MB x (fp16)
__device__ __half g_w1h[(size_t)E_ * 2 * FFN_ * HID_];   // 67 MB w1 (fp16)
__device__ __half g_w2h[(size_t)E_ * HID_ * FFN_];       // 34 MB w2 (fp16)

// ---------------- helpers ----------------
__device__ __forceinline__ void mma_f16(float* d, const uint32_t* a,
                                        const uint32_t* b, const float* c) {
    asm("mma.sync.aligned.m16n8k16.row.col.f32.f16.f16.f32 "
        "{%0,%1,%2,%3}, {%4,%5,%6,%7}, {%8,%9}, {%10,%11,%12,%13};\n"
        : "=f"(d[0]), "=f"(d[1]), "=f"(d[2]), "=f"(d[3])
        : "r"(a[0]), "r"(a[1]), "r"(a[2]), "r"(a[3]),
          "r"(b[0]), "r"(b[1]),
          "f"(c[0]), "f"(c[1]), "f"(c[2]), "f"(c[3]));
}
__device__ __forceinline__ void ldsm_x4(uint32_t& r0, uint32_t& r1,
                                        uint32_t& r2, uint32_t& r3, uint32_t addr) {
    asm volatile("ldmatrix.sync.aligned.m8n8.x4.shared.b16 {%0,%1,%2,%3}, [%4];"
                 : "=r"(r0), "=r"(r1), "=r"(r2), "=r"(r3) : "r"(addr));
}
__device__ __forceinline__ void cpa16(uint32_t saddr, const void* g) {
    asm volatile("cp.async.cg.shared.global [%0], [%1], 16;\n" :: "r"(saddr), "l"(g));
}
__device__ __forceinline__ void cpa_commit() { asm volatile("cp.async.commit_group;\n"); }
__device__ __forceinline__ void cpa_wait3()  { asm volatile("cp.async.wait_group 3;\n"); }
__device__ __forceinline__ void cpa_wait2()  { asm volatile("cp.async.wait_group 2;\n"); }
__device__ __forceinline__ void cpa_wait1()  { asm volatile("cp.async.wait_group 1;\n"); }
__device__ __forceinline__ void cpa_wait0()  { asm volatile("cp.async.wait_group 0;\n"); }
__device__ __forceinline__ uint32_t smem_u32(const void* p) {
    return (uint32_t)__cvta_generic_to_shared(p);
}

// ---------------- init / router / scan / place ----------------
__global__ void k_init(float* __restrict__ out) {
    int i = blockIdx.x * blockDim.x + threadIdx.x;
    if (i < E_) g_cnt[i] = 0;
    for (int j = i; j < OUT_MAIN; j += gridDim.x * blockDim.x) out[j] = 0.0f;
}

__global__ void k_router(const float* __restrict__ x,
                         const float* __restrict__ rw,
                         const float* __restrict__ rb,
                         float* __restrict__ out) {
    int warp = (blockIdx.x * blockDim.x + threadIdx.x) >> 5;
    int lane = threadIdx.x & 31;
    if (warp >= M_TOK) return;

    const float* xr = x + (size_t)warp * HID_;
    float xv[32];
#pragma unroll
    for (int i = 0; i < 32; i++) xv[i] = xr[lane + 32 * i];

    float logits[E_];
#pragma unroll
    for (int e = 0; e < E_; e++) {
        const float* w = rw + (size_t)e * HID_;
        float acc = 0.0f;
#pragma unroll
        for (int i = 0; i < 32; i++) acc += xv[i] * w[lane + 32 * i];
#pragma unroll
        for (int o = 16; o > 0; o >>= 1) acc += __shfl_xor_sync(0xffffffffu, acc, o);
        logits[e] = acc + rb[e];
    }

    if (lane == 0) {
        float mx = logits[0];
#pragma unroll
        for (int e = 1; e < E_; e++) mx = fmaxf(mx, logits[e]);
        float p[E_], s = 0.0f;
#pragma unroll
        for (int e = 0; e < E_; e++) { p[e] = expf(logits[e] - mx); s += p[e]; }
        float inv = 1.0f / s;
#pragma unroll
        for (int e = 0; e < E_; e++) p[e] *= inv;

        int i0 = 0;
#pragma unroll
        for (int e = 1; e < E_; e++) if (p[e] > p[i0]) i0 = e;
        int i1 = -1;
#pragma unroll
        for (int e = 0; e < E_; e++) {
            if (e == i0) continue;
            if (i1 < 0 || p[e] > p[i1]) i1 = e;
        }

        out[OUT_MAIN + warp * 2 + 0] = p[i0];
        out[OUT_MAIN + warp * 2 + 1] = p[i1];
        g_slot_e[warp * 2 + 0] = i0;  g_slot_w[warp * 2 + 0] = p[i0];
        g_slot_e[warp * 2 + 1] = i1;  g_slot_w[warp * 2 + 1] = p[i1];
        atomicAdd(&g_cnt[i0], 1);
        atomicAdd(&g_cnt[i1], 1);
    }
}

__global__ void k_scan() {
    if (threadIdx.x == 0) {
        int s = 0;
        for (int e = 0; e < E_; e++) { g_off[e] = s; g_cur[e] = s; s += g_cnt[e]; }
        g_off[E_] = s;
    }
}

__global__ void k_place() {
    int s = blockIdx.x * blockDim.x + threadIdx.x;
    if (s >= NSLOT) return;
    int e = g_slot_e[s];
    int p = atomicAdd(&g_cur[e], 1);
    g_tok[p] = s >> 1;
    g_w[p]   = g_slot_w[s];
}

// fp32 -> fp16 streaming convert (RN)
__global__ void k_cvt_h(const float4* __restrict__ src, uint2* __restrict__ dst, int n4) {
    int i = blockIdx.x * blockDim.x + threadIdx.x;
    int stride = gridDim.x * blockDim.x;
    for (; i < n4; i += stride) {
        float4 v = src[i];
        __half2 lo = __floats2half2_rn(v.x, v.y);
        __half2 hi = __floats2half2_rn(v.z, v.w);
        uint2 o;
        o.x = *(uint32_t*)&lo;
        o.y = *(uint32_t*)&hi;
        dst[i] = o;
    }
}

// ============================================================================
// GEMM1 (fp16 HMMA + ldmatrix): h = silu(x@Wg^T + bg) * (x@Wu^T + bu)
// ============================================================================
__global__ void __launch_bounds__(256, 2)
k_gemm1(const float* __restrict__ w1b) {
    int e = blockIdx.z;
    int rowEnd = g_off[e + 1];
    int row0 = g_off[e] + blockIdx.y * 128;
    if (row0 >= rowEnd) return;
    int nb = blockIdx.x * 64;

    extern __shared__ __half dsm[];
    __shared__ const __half* s_aptr[128];

    int tid  = threadIdx.x;
    int lane = tid & 31;
    int wid  = tid >> 5;
    int wm   = wid >> 2;
    int wn   = wid & 3;
    uint32_t sbase = smem_u32(dsm);

    for (int r = tid; r < 128; r += 256) {
        int gr = row0 + r;
        if (gr >= rowEnd) gr = rowEnd - 1;
        s_aptr[r] = g_xh + (size_t)g_tok[gr] * HID_;
    }
    __syncthreads();

    int rI[2], cI[2];
    const __half* bp[2];
#pragma unroll
    for (int i = 0; i < 2; i++) {
        int idx = tid + 256 * i;
        rI[i] = idx >> 2;
        cI[i] = (idx & 3) * 8;
        int r = rI[i];
        size_t wrow = (size_t)e * 2 * FFN_ + ((r & 1) ? (FFN_ + nb + (r >> 1)) : (nb + (r >> 1)));
        bp[i] = g_w1h + wrow * HID_;
    }

    auto load_tile = [&](int s, int k0) {
        uint32_t st = sbase + s * STAGE;
#pragma unroll
        for (int i = 0; i < 2; i++) {
            uint32_t off = (uint32_t)(rI[i] * LDSW + cI[i]) * 2;
            cpa16(st + off,        s_aptr[rI[i]] + k0 + cI[i]);
            cpa16(st + ABUF + off, bp[i] + k0 + cI[i]);
        }
        cpa_commit();
    };

    float acc[4][4][4];
#pragma unroll
    for (int mi = 0; mi < 4; mi++)
#pragma unroll
        for (int ni = 0; ni < 4; ni++)
#pragma unroll
            for (int q = 0; q < 4; q++) acc[mi][ni][q] = 0.0f;

    const int NT = HID_ / BK;   // 32
    load_tile(0, 0);
    load_tile(1, BK);
    load_tile(2, 2 * BK);

    int lr = lane >> 2;
    int lc = lane & 3;

    uint32_t a_loff = (uint32_t)((lane & 15) * ROWB + ((lane >> 4) & 1) * 16)
                    + (uint32_t)(wm * 64 * ROWB);
    uint32_t b_loff = (uint32_t)((((lane >> 4) & 1) * 8 + (lane & 7)) * ROWB
                    + ((lane >> 3) & 1) * 16)
                    + (uint32_t)(wn * 32 * ROWB);

    for (int kt = 0; kt < NT; kt++) {
        int buf = kt & (NSTG - 1);
        if (kt + 3 < NT)      { load_tile((kt + 3) & (NSTG - 1), (kt + 3) * BK); cpa_wait3(); }
        else if (kt + 2 < NT) { cpa_wait2(); }
        else if (kt + 1 < NT) { cpa_wait1(); }
        else                  { cpa_wait0(); }
        __syncthreads();

        uint32_t At = sbase + buf * STAGE;
        uint32_t Bt = At + ABUF;
#pragma unroll
        for (int s = 0; s < 2; s++) {
            uint32_t ks = s * 32;
            uint32_t a[4][4], b[4][2];
#pragma unroll
            for (int mi = 0; mi < 4; mi++)
                ldsm_x4(a[mi][0], a[mi][1], a[mi][2], a[mi][3],
                        At + (uint32_t)(mi * 16 * ROWB) + ks + a_loff);
#pragma unroll
            for (int nj = 0; nj < 2; nj++)
                ldsm_x4(b[2 * nj][0], b[2 * nj][1], b[2 * nj + 1][0], b[2 * nj + 1][1],
                        Bt + (uint32_t)(nj * 16 * ROWB) + ks + b_loff);
#pragma unroll
            for (int mi = 0; mi < 4; mi++)
#pragma unroll
                for (int ni = 0; ni < 4; ni++)
                    mma_f16(acc[mi][ni], a[mi], b[ni], acc[mi][ni]);
        }
        __syncthreads();
    }

    const float* bg_base = w1b + (size_t)e * 2 * FFN_;
    const float* bu_base = bg_base + FFN_;
#pragma unroll
    for (int mi = 0; mi < 4; mi++) {
        int r = row0 + wm * 64 + mi * 16 + lr;
#pragma unroll
        for (int ni = 0; ni < 4; ni++) {
            int gj = nb + wn * 16 + ni * 4 + lc;
            float bg = bg_base[gj];
            float bu = bu_base[gj];
            if (r < rowEnd) {
                float g = acc[mi][ni][0] + bg;
                float u = acc[mi][ni][1] + bu;
                g_hh[(size_t)r * FFN_ + gj] = __float2half_rn((g / (1.0f + expf(-g))) * u);
            }
            if (r + 8 < rowEnd) {
                float g = acc[mi][ni][2] + bg;
                float u = acc[mi][ni][3] + bu;
                g_hh[(size_t)(r + 8) * FFN_ + gj] = __float2half_rn((g / (1.0f + expf(-g))) * u);
            }
        }
    }
}

// ============================================================================
// GEMM2 (fp16 HMMA + ldmatrix): out[tok] += w * (h@W2^T + b2)
// ============================================================================
__global__ void __launch_bounds__(256, 2)
k_gemm2(const float* __restrict__ w2b, float* __restrict__ out) {
    int e = blockIdx.z;
    int rowEnd = g_off[e + 1];
    int row0 = g_off[e] + blockIdx.y * 128;
    if (row0 >= rowEnd) return;
    int nb = blockIdx.x * 128;

    extern __shared__ __half dsm[];

    int tid  = threadIdx.x;
    int lane = tid & 31;
    int wid  = tid >> 5;
    int wm   = wid >> 2;
    int wn   = wid & 3;
    uint32_t sbase = smem_u32(dsm);

    int rI[2], cI[2];
    const __half* ap[2];
    const __half* bp[2];
#pragma unroll
    for (int i = 0; i < 2; i++) {
        int idx = tid + 256 * i;
        rI[i] = idx >> 2;
        cI[i] = (idx & 3) * 8;
        int gr = row0 + rI[i];
        if (gr >= rowEnd) gr = rowEnd - 1;
        ap[i] = g_hh + (size_t)gr * FFN_;
        bp[i] = g_w2h + ((size_t)e * HID_ + (nb + rI[i])) * FFN_;
    }

    auto load_tile = [&](int s, int k0) {
        uint32_t st = sbase + s * STAGE;
#pragma unroll
        for (int i = 0; i < 2; i++) {
            uint32_t off = (uint32_t)(rI[i] * LDSW + cI[i]) * 2;
            cpa16(st + off,        ap[i] + k0 + cI[i]);
            cpa16(st + ABUF + off, bp[i] + k0 + cI[i]);
        }
        cpa_commit();
    };

    float acc[4][4][4];
#pragma unroll
    for (int mi = 0; mi < 4; mi++)
#pragma unroll
        for (int ni = 0; ni < 4; ni++)
#pragma unroll
            for (int q = 0; q < 4; q++) acc[mi][ni][q] = 0.0f;

    const int NT = FFN_ / BK;   // 64
    load_tile(0, 0);
    load_tile(1, BK);
    load_tile(2, 2 * BK);

    int lr = lane >> 2;
    int lc = lane & 3;

    uint32_t a_loff = (uint32_t)((lane & 15) * ROWB + ((lane >> 4) & 1) * 16)
                    + (uint32_t)(wm * 64 * ROWB);
    uint32_t b_loff = (uint32_t)((((lane >> 4) & 1) * 8 + (lane & 7)) * ROWB
                    + ((lane >> 3) & 1) * 16)
                    + (uint32_t)(wn * 32 * ROWB);

    for (int kt = 0; kt < NT; kt++) {
        int buf = kt & (NSTG - 1);
        if (kt + 3 < NT)      { load_tile((kt + 3) & (NSTG - 1), (kt + 3) * BK); cpa_wait3(); }
        else if (kt + 2 < NT) { cpa_wait2(); }
        else if (kt + 1 < NT) { cpa_wait1(); }
        else                  { cpa_wait0(); }
        __syncthreads();

        uint32_t At = sbase + buf * STAGE;
        uint32_t Bt = At + ABUF;
#pragma unroll
        for (int s = 0; s < 2; s++) {
            uint32_t ks = s * 32;
            uint32_t a[4][4], b[4][2];
#pragma unroll
            for (int mi = 0; mi < 4; mi++)
                ldsm_x4(a[mi][0], a[mi][1], a[mi][2], a[mi][3],
                        At + (uint32_t)(mi * 16 * ROWB) + ks + a_loff);
#pragma unroll
            for (int nj = 0; nj < 2; nj++)
                ldsm_x4(b[2 * nj][0], b[2 * nj][1], b[2 * nj + 1][0], b[2 * nj + 1][1],
                        Bt + (uint32_t)(nj * 16 * ROWB) + ks + b_loff);
#pragma unroll
            for (int mi = 0; mi < 4; mi++)
#pragma unroll
                for (int ni = 0; ni < 4; ni++)
                    mma_f16(acc[mi][ni], a[mi], b[ni], acc[mi][ni]);
        }
        __syncthreads();
    }

    const float* b2 = w2b + (size_t)e * HID_;
#pragma unroll
    for (int mi = 0; mi < 4; mi++) {
        int r = row0 + wm * 64 + mi * 16 + lr;
#pragma unroll
        for (int ni = 0; ni < 4; ni++) {
            int c = nb + wn * 32 + ni * 8 + lc * 2;
            float b0 = b2[c], b1 = b2[c + 1];
            if (r < rowEnd) {
                int tok = g_tok[r]; float w = g_w[r];
                atomicAdd(&out[(size_t)tok * HID_ + c],     (acc[mi][ni][0] + b0) * w);
                atomicAdd(&out[(size_t)tok * HID_ + c + 1], (acc[mi][ni][1] + b1) * w);
            }
            if (r + 8 < rowEnd) {
                int tok = g_tok[r + 8]; float w = g_w[r + 8];
                atomicAdd(&out[(size_t)tok * HID_ + c],     (acc[mi][ni][2] + b0) * w);
                atomicAdd(&out[(size_t)tok * HID_ + c + 1], (acc[mi][ni][3] + b1) * w);
            }
        }
    }
}

// ---------------- launch ----------------
extern "C" void kernel_launch(void* const* d_in, const int* in_sizes, int n_in,
                              void* d_out, int out_size) {
    (void)in_sizes; (void)n_in; (void)out_size;
    const float* x   = (const float*)d_in[0];
    const float* rw  = (const float*)d_in[1];
    const float* rb  = (const float*)d_in[2];
    const float* w1  = (const float*)d_in[3];
    const float* w1b = (const float*)d_in[4];
    const float* w2  = (const float*)d_in[5];
    const float* w2b = (const float*)d_in[6];
    float* out = (float*)d_out;

    static cudaStream_t s2 = nullptr;
    static cudaEvent_t evFork = nullptr, evW1 = nullptr, evW2 = nullptr;
    if (!s2) {
        cudaStreamCreateWithFlags(&s2, cudaStreamNonBlocking);
        cudaEventCreateWithFlags(&evFork, cudaEventDisableTiming);
        cudaEventCreateWithFlags(&evW1,  cudaEventDisableTiming);
        cudaEventCreateWithFlags(&evW2,  cudaEventDisableTiming);
    }

    cudaFuncSetAttribute(k_gemm1, cudaFuncAttributeMaxDynamicSharedMemorySize, NSTG * STAGE);
    cudaFuncSetAttribute(k_gemm2, cudaFuncAttributeMaxDynamicSharedMemorySize, NSTG * STAGE);

    __half* xh;  cudaGetSymbolAddress((void**)&xh,  g_xh);
    __half* w1h; cudaGetSymbolAddress((void**)&w1h, g_w1h);
    __half* w2h; cudaGetSymbolAddress((void**)&w2h, g_w2h);

    // fork: weight converts run on s2, concurrent with router chain + GEMM1
    cudaEventRecord(evFork, 0);
    cudaStreamWaitEvent(s2, evFork, 0);
    k_cvt_h<<<2048, 256, 0, s2>>>((const float4*)w1, (uint2*)w1h, (E_ * 2 * FFN_ * HID_) / 4);
    cudaEventRecord(evW1, s2);
    k_cvt_h<<<2048, 256, 0, s2>>>((const float4*)w2, (uint2*)w2h, (E_ * HID_ * FFN_) / 4);
    cudaEventRecord(evW2, s2);

    // main stream: routing chain + x convert
    k_init<<<1024, 256>>>(out);
    k_router<<<M_TOK / 8, 256>>>(x, rw, rb, out);
    k_scan<<<1, 32>>>();
    k_place<<<NSLOT / 256, 256>>>();
    k_cvt_h<<<512, 256>>>((const float4*)x, (uint2*)xh, (M_TOK * HID_) / 4);

    // join: GEMM1 needs w1h, GEMM2 needs w2h
    cudaStreamWaitEvent(0, evW1, 0);
    dim3 g1(FFN_ / 64, NSLOT / 128, E_);
    k_gemm1<<<g1, 256, NSTG * STAGE>>>(w1b);

    cudaStreamWaitEvent(0, evW2, 0);
    dim3 g2(HID_ / 128, NSLOT / 128, E_);
    k_gemm2<<<g2, 256, NSTG * STAGE>>>(w2b, out);
}